// round 14
// speedup vs baseline: 6.7463x; 1.0077x over previous
#include <cuda_runtime.h>
#include <cuda_bf16.h>
#include <math.h>
#include <stdint.h>

// Problem constants
#define Bz    2
#define SEQ   2048
#define DIM   1024
#define NHEAD 16
#define HDIM  64
#define FF    4096
#define NTOK  (Bz * SEQ)   // 4096

// tcgen05 availability for THIS compilation pass (arch- or family-specific >= sm_100)
#if defined(__CUDA_ARCH_FEAT_SM103_ALL) || defined(__CUDA_ARCH_FEAT_SM100_ALL) || \
    defined(__CUDA_ARCH_FEAT_SM101_ALL) ||                                        \
    (defined(__CUDA_ARCH_SPECIFIC__) && (__CUDA_ARCH_SPECIFIC__ >= 1000)) ||       \
    (defined(__CUDA_ARCH_FAMILY_SPECIFIC__) && (__CUDA_ARCH_FAMILY_SPECIFIC__ >= 1000))
#define TC_OK 1
#else
#define TC_OK 0
#endif

// ======================= scratch (device globals) ==========================
__device__ __align__(16) __nv_bfloat16 g_xln1_hi[NTOK * DIM];
__device__ __align__(16) __nv_bfloat16 g_xln1_lo[NTOK * DIM];
__device__ __align__(16) __nv_bfloat16 g_q_hi[NTOK * DIM], g_q_lo[NTOK * DIM];
__device__ __align__(16) __nv_bfloat16 g_k_hi[NTOK * DIM], g_k_lo[NTOK * DIM];
__device__ __align__(16) __nv_bfloat16 g_vt_hi[NTOK * DIM], g_vt_lo[NTOK * DIM]; // [b,h,hd,s]
__device__ __align__(16) __nv_bfloat16 g_attn_hi[NTOK * DIM];
__device__ __align__(16) __nv_bfloat16 g_attn_lo[NTOK * DIM];
__device__ __align__(16) float         g_feat[NTOK * DIM];
__device__ __align__(16) __nv_bfloat16 g_xln2_hi[NTOK * DIM];
__device__ __align__(16) __nv_bfloat16 g_xln2_lo[NTOK * DIM];
__device__ __align__(16) __nv_bfloat16 g_h1_hi[NTOK * FF];
__device__ __align__(16) __nv_bfloat16 g_h1_lo[NTOK * FF];
// transposed bf16 weights [N,K]; QKV fused: rows 0-1023 Q, 1024-2047 K, 2048-3071 V
__device__ __align__(16) __nv_bfloat16 g_wqkvT_hi[3 * DIM * DIM], g_wqkvT_lo[3 * DIM * DIM];
__device__ __align__(16) __nv_bfloat16 g_woT_hi[DIM * DIM], g_woT_lo[DIM * DIM];
__device__ __align__(16) __nv_bfloat16 g_w1T_hi[DIM * FF],  g_w1T_lo[DIM * FF];
__device__ __align__(16) __nv_bfloat16 g_w2T_hi[FF * DIM],  g_w2T_lo[FF * DIM];

// ======================= common helpers ====================================
__device__ __forceinline__ void bsplit(float v, __nv_bfloat16& h, __nv_bfloat16& l) {
    h = __float2bfloat16_rn(v);
    l = __float2bfloat16_rn(v - __bfloat162float(h));
}
__device__ __forceinline__ float gelu_f(float x) {
    return 0.5f * x * (1.0f + erff(x * 0.70710678118654752f));
}

#if TC_OK
// ======================= tcgen05 PTX helpers (sm_103a pass only) ===========
__device__ __forceinline__ uint32_t smem_u32(const void* p) {
    uint32_t a;
    asm("{ .reg .u64 t; cvta.to.shared.u64 t, %1; cvt.u32.u64 %0, t; }"
        : "=r"(a) : "l"(p));
    return a;
}
__device__ __forceinline__ uint32_t elect_one() {
    uint32_t pred;
    asm volatile("{\n\t.reg .pred p;\n\telect.sync _|p, 0xFFFFFFFF;\n\t"
                 "selp.b32 %0, 1, 0, p;\n\t}" : "=r"(pred));
    return pred;
}
__device__ __forceinline__ void mbar_init(uint32_t mbar, uint32_t cnt) {
    asm volatile("mbarrier.init.shared.b64 [%0], %1;" :: "r"(mbar), "r"(cnt) : "memory");
}
__device__ __forceinline__ void mbar_wait(uint32_t mbar, uint32_t parity) {
    asm volatile(
        "{\n\t.reg .pred P1;\n\t"
        "WAIT_LOOP_%=:\n\t"
        "mbarrier.try_wait.parity.acquire.cta.shared::cta.b64 P1, [%0], %1, 0x989680;\n\t"
        "@P1 bra.uni WAIT_DONE_%=;\n\t"
        "bra.uni WAIT_LOOP_%=;\n\t"
        "WAIT_DONE_%=:\n\t}"
        :: "r"(mbar), "r"(parity) : "memory");
}
// .noinc: arrival counts against the barrier's initialized expected count.
__device__ __forceinline__ void cp_mbar_arrive_noinc(uint32_t mbar) {
    asm volatile("cp.async.mbarrier.arrive.noinc.shared::cta.b64 [%0];"
                 :: "r"(mbar) : "memory");
}
__device__ __forceinline__ void tmem_alloc(uint32_t dst_smem, uint32_t ncols) {
    asm volatile("tcgen05.alloc.cta_group::1.sync.aligned.shared::cta.b32 [%0], %1;"
                 :: "r"(dst_smem), "r"(ncols) : "memory");
}
__device__ __forceinline__ void tmem_dealloc(uint32_t tmem, uint32_t ncols) {
    asm volatile("tcgen05.dealloc.cta_group::1.sync.aligned.b32 %0, %1;"
                 :: "r"(tmem), "r"(ncols));
}
__device__ __forceinline__ void tmem_relinquish() {
    asm volatile("tcgen05.relinquish_alloc_permit.cta_group::1.sync.aligned;");
}
__device__ __forceinline__ void tc_commit(uint32_t mbar) {
    asm volatile("tcgen05.commit.cta_group::1.mbarrier::arrive::one.shared::cluster.b64 [%0];"
                 :: "r"(mbar) : "memory");
}
__device__ __forceinline__ void tc_fence_after() {
    asm volatile("tcgen05.fence::after_thread_sync;" ::: "memory");
}
__device__ __forceinline__ void tc_fence_before() {
    asm volatile("tcgen05.fence::before_thread_sync;" ::: "memory");
}
__device__ __forceinline__ void fence_proxy_async_shared() {
    asm volatile("fence.proxy.async.shared::cta;" ::: "memory");
}
__device__ __forceinline__ void mma_f16_ss(uint32_t d, uint64_t ad, uint64_t bd,
                                           uint32_t idesc, uint32_t en) {
    asm volatile(
        "{\n\t.reg .pred p;\n\tsetp.ne.u32 p, %5, 0;\n\t"
        "tcgen05.mma.cta_group::1.kind::f16 [%0], %1, %2, %3, {%4, %4, %4, %4}, p;\n\t}"
        :: "r"(d), "l"(ad), "l"(bd), "r"(idesc), "r"(0u), "r"(en) : "memory");
}
__device__ __forceinline__ void tmem_ld32(uint32_t* r, uint32_t addr) {
    asm volatile(
        "tcgen05.ld.sync.aligned.32x32b.x32.b32 "
        "{%0, %1, %2, %3, %4, %5, %6, %7, "
        " %8, %9, %10, %11, %12, %13, %14, %15, "
        " %16, %17, %18, %19, %20, %21, %22, %23, "
        " %24, %25, %26, %27, %28, %29, %30, %31}, [%32];"
        : "=r"(r[0]), "=r"(r[1]), "=r"(r[2]), "=r"(r[3]),
          "=r"(r[4]), "=r"(r[5]), "=r"(r[6]), "=r"(r[7]),
          "=r"(r[8]), "=r"(r[9]), "=r"(r[10]), "=r"(r[11]),
          "=r"(r[12]), "=r"(r[13]), "=r"(r[14]), "=r"(r[15]),
          "=r"(r[16]), "=r"(r[17]), "=r"(r[18]), "=r"(r[19]),
          "=r"(r[20]), "=r"(r[21]), "=r"(r[22]), "=r"(r[23]),
          "=r"(r[24]), "=r"(r[25]), "=r"(r[26]), "=r"(r[27]),
          "=r"(r[28]), "=r"(r[29]), "=r"(r[30]), "=r"(r[31])
        : "r"(addr));
}
__device__ __forceinline__ void tmem_wait_ld() {
    asm volatile("tcgen05.wait::ld.sync.aligned;" ::: "memory");
}
__device__ __forceinline__ void cpasync16(uint32_t dst, const void* src) {
    asm volatile("cp.async.cg.shared.global [%0], [%1], 16;" :: "r"(dst), "l"(src));
}
__device__ __forceinline__ void cp_commit() {
    asm volatile("cp.async.commit_group;" ::: "memory");
}
__device__ __forceinline__ void cp_wait1() {
    asm volatile("cp.async.wait_group 1;" ::: "memory");
}
__device__ __forceinline__ void cp_wait2() {
    asm volatile("cp.async.wait_group 2;" ::: "memory");
}
// SW128 SMEM descriptor (128B rows): layout 2, version 1, SBO=64, LBO=1
__device__ __forceinline__ uint64_t make_desc(uint32_t addr) {
    const uint64_t base =
        (uint64_t(2) << 61) | (uint64_t(1) << 46) | (uint64_t(64) << 32) | (uint64_t(1) << 16);
    return base | ((uint64_t)(addr >> 4) & 0x3FFF);
}
// SW64 SMEM descriptor (64B rows): layout 4, version 1, SBO=32, LBO=1
__device__ __forceinline__ uint64_t make_desc64(uint32_t addr) {
    const uint64_t base =
        (uint64_t(4) << 61) | (uint64_t(1) << 46) | (uint64_t(32) << 32) | (uint64_t(1) << 16);
    return base | ((uint64_t)(addr >> 4) & 0x3FFF);
}
#endif  // TC_OK

// ======================= LayerNorm -> bf16 hi/lo ===========================
__global__ __launch_bounds__(256)
void ln_kernel(const float* __restrict__ x, const float* __restrict__ g,
               const float* __restrict__ b,
               __nv_bfloat16* __restrict__ y_hi, __nv_bfloat16* __restrict__ y_lo)
{
    const int row = blockIdx.x;
    const int t = threadIdx.x;
    const float4 v = ((const float4*)(x + (size_t)row * DIM))[t];

    float s = v.x + v.y + v.z + v.w;
    __shared__ float sh[8];
#pragma unroll
    for (int o = 16; o > 0; o >>= 1) s += __shfl_xor_sync(0xffffffffu, s, o);
    if ((t & 31) == 0) sh[t >> 5] = s;
    __syncthreads();
    float tot = 0.f;
#pragma unroll
    for (int i = 0; i < 8; i++) tot += sh[i];
    const float mu = tot * (1.0f / DIM);

    const float dx = v.x - mu, dy = v.y - mu, dz = v.z - mu, dw = v.w - mu;
    float sq = dx * dx + dy * dy + dz * dz + dw * dw;
#pragma unroll
    for (int o = 16; o > 0; o >>= 1) sq += __shfl_xor_sync(0xffffffffu, sq, o);
    __syncthreads();
    if ((t & 31) == 0) sh[t >> 5] = sq;
    __syncthreads();
    float v2 = 0.f;
#pragma unroll
    for (int i = 0; i < 8; i++) v2 += sh[i];
    const float rstd = rsqrtf(v2 * (1.0f / DIM) + 1e-5f);

    const float4 gg = ((const float4*)g)[t];
    const float4 bb = ((const float4*)b)[t];
    float o0 = dx * rstd * gg.x + bb.x;
    float o1 = dy * rstd * gg.y + bb.y;
    float o2 = dz * rstd * gg.z + bb.z;
    float o3 = dw * rstd * gg.w + bb.w;

    __nv_bfloat16 h0, h1, h2, h3, l0, l1, l2, l3;
    bsplit(o0, h0, l0); bsplit(o1, h1, l1); bsplit(o2, h2, l2); bsplit(o3, h3, l3);
    ((ushort4*)(y_hi + (size_t)row * DIM))[t] =
        make_ushort4(__bfloat16_as_ushort(h0), __bfloat16_as_ushort(h1),
                     __bfloat16_as_ushort(h2), __bfloat16_as_ushort(h3));
    ((ushort4*)(y_lo + (size_t)row * DIM))[t] =
        make_ushort4(__bfloat16_as_ushort(l0), __bfloat16_as_ushort(l1),
                     __bfloat16_as_ushort(l2), __bfloat16_as_ushort(l3));
}

// ============ fused weight transpose + bf16 split (all 6 weights) ==========
// Q/K/V write into ONE fused [3*DIM, DIM] buffer (rows: Q 0-1023, K 1024-2047,
// V 2048-3071) so QKV can run as a single GEMM.
__global__ __launch_bounds__(256)
void wtrans_all(const float* __restrict__ wq, const float* __restrict__ wk,
                const float* __restrict__ wv, const float* __restrict__ wo,
                const float* __restrict__ w1, const float* __restrict__ w2,
                __nv_bfloat16* qkvh, __nv_bfloat16* qkvl,
                __nv_bfloat16* oh, __nv_bfloat16* ol,
                __nv_bfloat16* f1h, __nv_bfloat16* f1l,
                __nv_bfloat16* f2h, __nv_bfloat16* f2l)
{
    int id = blockIdx.x;
    const float* W;
    __nv_bfloat16 *bh, *bl;
    int K, N;
    if (id < 4096) {
        const int s = id >> 10;
        id &= 1023;
        K = DIM; N = DIM;
        W  = (s == 0) ? wq : (s == 1) ? wk : (s == 2) ? wv : wo;
        if (s < 3) { bh = qkvh + (size_t)s * DIM * DIM; bl = qkvl + (size_t)s * DIM * DIM; }
        else       { bh = oh; bl = ol; }
    } else if (id < 8192) {
        id -= 4096; W = w1; K = DIM; N = FF; bh = f1h; bl = f1l;
    } else {
        id -= 8192; W = w2; K = FF; N = DIM; bh = f2h; bl = f2l;
    }
    const int nx = N / 32;
    const int n0 = (id % nx) * 32, k0 = (id / nx) * 32;

    __shared__ float t[32][33];
    const int tx = threadIdx.x & 31, ty = threadIdx.x >> 5;
#pragma unroll
    for (int i = 0; i < 4; i++) {
        const int r = ty + i * 8;
        t[r][tx] = W[(size_t)(k0 + r) * N + n0 + tx];
    }
    __syncthreads();
#pragma unroll
    for (int i = 0; i < 4; i++) {
        const int r = ty + i * 8;
        const float v = t[tx][r];
        __nv_bfloat16 h, l;
        bsplit(v, h, l);
        const size_t o = (size_t)(n0 + r) * K + k0 + tx;
        bh[o] = h;
        bl[o] = l;
    }
}

// ======================= shared epilogue helper ============================
#if TC_OK
template <int MODE>
__device__ __forceinline__ void gemm_epilogue_cols(
    uint32_t tmem, int m0, int n0, int ncols, int tid,
    const float* __restrict__ bias, const float* __restrict__ res,
    float* __restrict__ out_f, __nv_bfloat16* __restrict__ out_hi,
    __nv_bfloat16* __restrict__ out_lo, int N)
{
    const int w = tid >> 5, lane = tid & 31;
    const int row = m0 + w * 32 + lane;
    for (int c0 = 0; c0 < ncols; c0 += 32) {
        uint32_t dreg[32];
        tmem_ld32(dreg, tmem + c0);
        tmem_wait_ld();
        const int colbase = n0 + c0;
        if (MODE == 2 || MODE == 3) {
#pragma unroll
            for (int j0 = 0; j0 < 32; j0 += 8) {
                ushort hs[8], ls[8];
#pragma unroll
                for (int jj = 0; jj < 8; jj++) {
                    float v = __uint_as_float(dreg[j0 + jj]) + bias[colbase + j0 + jj];
                    if (MODE == 2) v = gelu_f(v);
                    __nv_bfloat16 h, l;
                    bsplit(v, h, l);
                    hs[jj] = __bfloat16_as_ushort(h);
                    ls[jj] = __bfloat16_as_ushort(l);
                }
                const size_t o = (size_t)row * N + colbase + j0;
                *(ushort4*)(out_hi + o)     = make_ushort4(hs[0], hs[1], hs[2], hs[3]);
                *(ushort4*)(out_hi + o + 4) = make_ushort4(hs[4], hs[5], hs[6], hs[7]);
                *(ushort4*)(out_lo + o)     = make_ushort4(ls[0], ls[1], ls[2], ls[3]);
                *(ushort4*)(out_lo + o + 4) = make_ushort4(ls[4], ls[5], ls[6], ls[7]);
            }
        } else if (MODE == 4) {
            const int b = row >> 11, s = row & 2047;
#pragma unroll
            for (int jj = 0; jj < 32; jj++) {
                const int c = colbase + jj;
                float v = __uint_as_float(dreg[jj]) + bias[c];
                __nv_bfloat16 h, l;
                bsplit(v, h, l);
                const size_t o = (((size_t)b * NHEAD + (c >> 6)) * HDIM + (c & 63)) * SEQ + s;
                out_hi[o] = h;
                out_lo[o] = l;
            }
        } else {  // MODE 1
            float* op = out_f + (size_t)row * N + colbase;
            const float* rp = res + (size_t)row * N + colbase;
#pragma unroll
            for (int j0 = 0; j0 < 32; j0 += 4) {
                float4 ov;
                ov.x = __uint_as_float(dreg[j0 + 0]) + bias[colbase + j0 + 0];
                ov.y = __uint_as_float(dreg[j0 + 1]) + bias[colbase + j0 + 1];
                ov.z = __uint_as_float(dreg[j0 + 2]) + bias[colbase + j0 + 2];
                ov.w = __uint_as_float(dreg[j0 + 3]) + bias[colbase + j0 + 3];
                const float4 rv = *(const float4*)(rp + j0);
                ov.x += rv.x; ov.y += rv.y; ov.z += rv.z; ov.w += rv.w;
                *(float4*)(op + j0) = ov;
            }
        }
    }
    tc_fence_before();
}
#endif

// ======================= wide GEMM mainloop (shared) =======================
#define WST       4
#define AH_T      8192
#define BH_T      16384
#define WSTAGE_B  (2 * AH_T + 2 * BH_T)      // 49152
#define GSMEM_W   (WST * WSTAGE_B + 1024)
#define GTHREADS  160

#if TC_OK
// Runs the warp-specialized 128x256 mainloop; on return the 256-col TMEM
// accumulator is complete. All threads participate.
__device__ __forceinline__ void wide_mainloop(
    uint32_t sbase, uint32_t tmem, uint32_t full_b, uint32_t empty_b,
    const __nv_bfloat16* a_hi, const __nv_bfloat16* a_lo,
    const __nv_bfloat16* b_hi, const __nv_bfloat16* b_lo,
    int m0, int n0, int K, int tid)
{
    const int T = K >> 5;
    constexpr uint32_t IDESC =
        (1u << 4) | (1u << 7) | (1u << 10) | ((128u / 8u) << 17) | ((128u / 16u) << 24);

    if (tid >= 32) {
        const int ltid = tid - 32;
        for (int lt = 0; lt < T; lt++) {
            const int s = lt & 3, pass = lt >> 2;
            if (pass >= 1) mbar_wait(empty_b + s * 8, (uint32_t)((pass - 1) & 1));
            const uint32_t sdst = sbase + s * WSTAGE_B;
            const int kc = (lt << 5);
#pragma unroll
            for (int i = 0; i < 24; i++) {
                const int c = ltid + i * 128;
                const __nv_bfloat16* srcp;
                uint32_t dst;
                if (c < 1024) {
                    const int idx = c & 511;
                    const int row = idx >> 2, ch = idx & 3;
                    const uint32_t off = (uint32_t)(row * 64 + ch * 16);
                    const uint32_t sw = off ^ ((off >> 3) & 0x30);
                    srcp = ((c < 512) ? a_hi : a_lo) + (size_t)(m0 + row) * K + kc + ch * 8;
                    dst = sdst + ((c < 512) ? 0u : (uint32_t)AH_T) + sw;
                } else {
                    const int idx = c & 1023;
                    const int row = idx >> 2, ch = idx & 3;
                    const uint32_t off = (uint32_t)(row * 64 + ch * 16);
                    const uint32_t sw = off ^ ((off >> 3) & 0x30);
                    srcp = ((c < 2048) ? b_hi : b_lo) + (size_t)(n0 + row) * K + kc + ch * 8;
                    dst = sdst + ((c < 2048) ? (uint32_t)(2 * AH_T)
                                             : (uint32_t)(2 * AH_T + BH_T)) + sw;
                }
                cpasync16(dst, srcp);
            }
            cp_mbar_arrive_noinc(full_b + s * 8);
        }
    } else if (elect_one()) {
        tc_fence_after();
        for (int kt = 0; kt < T; kt++) {
            const int s = kt & 3, pass = kt >> 2;
            mbar_wait(full_b + s * 8, (uint32_t)(pass & 1));
            const uint32_t st = sbase + s * WSTAGE_B;
            const uint64_t dAhi = make_desc64(st);
            const uint64_t dAlo = make_desc64(st + AH_T);
            const uint64_t dB0hi = make_desc64(st + 2 * AH_T);
            const uint64_t dB1hi = make_desc64(st + 2 * AH_T + 8192);
            const uint64_t dB0lo = make_desc64(st + 2 * AH_T + BH_T);
            const uint64_t dB1lo = make_desc64(st + 2 * AH_T + BH_T + 8192);
#pragma unroll
            for (int ks = 0; ks < 2; ks++) {
                const uint32_t en = (kt > 0 || ks > 0) ? 1u : 0u;
                mma_f16_ss(tmem,       dAhi + ks * 2, dB0hi + ks * 2, IDESC, en);
                mma_f16_ss(tmem + 128, dAhi + ks * 2, dB1hi + ks * 2, IDESC, en);
                mma_f16_ss(tmem,       dAlo + ks * 2, dB0hi + ks * 2, IDESC, 1u);
                mma_f16_ss(tmem + 128, dAlo + ks * 2, dB1hi + ks * 2, IDESC, 1u);
                mma_f16_ss(tmem,       dAhi + ks * 2, dB0lo + ks * 2, IDESC, 1u);
                mma_f16_ss(tmem + 128, dAhi + ks * 2, dB1lo + ks * 2, IDESC, 1u);
            }
            tc_commit(empty_b + s * 8);
        }
    }

    {
        const int last = (K >> 5) - 1;
        mbar_wait(empty_b + (last & 3) * 8, (uint32_t)((last >> 2) & 1));
    }
    __syncthreads();
    tc_fence_after();
}
#endif

// ===== GEMM WIDE (generic epilogue modes) ==================================
template <int MODE>
__global__ __launch_bounds__(GTHREADS, 1)
void gemm_tcw(const __nv_bfloat16* __restrict__ a_hi, const __nv_bfloat16* __restrict__ a_lo,
              const __nv_bfloat16* __restrict__ b_hi, const __nv_bfloat16* __restrict__ b_lo,
              const float* __restrict__ bias, const float* __restrict__ res,
              float* __restrict__ out_f, __nv_bfloat16* __restrict__ out_hi,
              __nv_bfloat16* __restrict__ out_lo, int M, int N, int K)
{
#if TC_OK
    extern __shared__ char dynsmem[];
    __shared__ uint32_t sh_tmem;
    __shared__ __align__(8) uint64_t sh_full[WST];
    __shared__ __align__(8) uint64_t sh_empty[WST];

    const int tid = threadIdx.x;
    const int m0 = blockIdx.y * 128;
    const int n0 = blockIdx.x * 256;

    uint32_t sbase = smem_u32(dynsmem);
    sbase = (sbase + 1023u) & ~1023u;
    const uint32_t full_b = smem_u32(sh_full);
    const uint32_t empty_b = smem_u32(sh_empty);

    if (tid < 32) {
        tmem_alloc(smem_u32(&sh_tmem), 256);
        tmem_relinquish();
    }
    if (tid == 0) {
#pragma unroll
        for (int s = 0; s < WST; s++) {
            mbar_init(full_b + s * 8, 128);
            mbar_init(empty_b + s * 8, 1);
        }
    }
    __syncthreads();
    const uint32_t tmem = sh_tmem;

    wide_mainloop(sbase, tmem, full_b, empty_b, a_hi, a_lo, b_hi, b_lo, m0, n0, K, tid);

    if (tid < 128)
        gemm_epilogue_cols<MODE>(tmem, m0, n0, 256, tid, bias, res, out_f, out_hi, out_lo, N);
    __syncthreads();
    if (tid < 32) tmem_dealloc(tmem, 256);

#else
    // FFMA fallback (correctness only)
    __shared__ float As[16][128];
    __shared__ float Bs[16][32];
    const int tid = threadIdx.x;
    const int m0 = blockIdx.y * 128;
    const int n0 = blockIdx.x * 256;
    const int row = m0 + (tid & 127);
    for (int p = 0; p < 8; p++) {
        const int c0 = n0 + p * 32;
        float acc[32];
#pragma unroll
        for (int j = 0; j < 32; j++) acc[j] = 0.f;
        for (int kt = 0; kt < K; kt += 16) {
            __syncthreads();
            for (int i = tid; i < 16 * 128; i += GTHREADS) {
                const int kk = i >> 7, r = i & 127;
                const size_t g = (size_t)(m0 + r) * K + kt + kk;
                As[kk][r] = __bfloat162float(a_hi[g]) + __bfloat162float(a_lo[g]);
            }
            for (int i = tid; i < 16 * 32; i += GTHREADS) {
                const int kk = i >> 5, r = i & 31;
                const size_t g = (size_t)(c0 + r) * K + kt + kk;
                Bs[kk][r] = __bfloat162float(b_hi[g]) + __bfloat162float(b_lo[g]);
            }
            __syncthreads();
            if (tid < 128) {
#pragma unroll
                for (int kk = 0; kk < 16; kk++) {
                    const float a = As[kk][tid];
#pragma unroll
                    for (int j = 0; j < 32; j++) acc[j] = fmaf(a, Bs[kk][j], acc[j]);
                }
            }
        }
        if (tid < 128) {
#pragma unroll
            for (int j = 0; j < 32; j++) {
                const int c = c0 + j;
                float v = acc[j] + bias[c];
                if (MODE == 1) {
                    out_f[(size_t)row * N + c] = v + res[(size_t)row * N + c];
                } else if (MODE == 4) {
                    __nv_bfloat16 h, l;
                    bsplit(v, h, l);
                    const int b = row >> 11, s = row & 2047;
                    const size_t o = (((size_t)b * NHEAD + (c >> 6)) * HDIM + (c & 63)) * SEQ + s;
                    out_hi[o] = h;
                    out_lo[o] = l;
                } else {
                    if (MODE == 2) v = gelu_f(v);
                    __nv_bfloat16 h, l;
                    bsplit(v, h, l);
                    out_hi[(size_t)row * N + c] = h;
                    out_lo[(size_t)row * N + c] = l;
                }
            }
        }
        __syncthreads();
    }
#endif
}

// ===== FUSED QKV GEMM: one launch, N=3072, per-tile output routing =========
// Tile columns n0 = bx*256 lie entirely in one of Q (n0<1024), K (<2048), V.
__global__ __launch_bounds__(GTHREADS, 1)
void gemm_qkv(const __nv_bfloat16* __restrict__ a_hi, const __nv_bfloat16* __restrict__ a_lo,
              const __nv_bfloat16* __restrict__ b_hi, const __nv_bfloat16* __restrict__ b_lo,
              const float* __restrict__ bq, const float* __restrict__ bk,
              const float* __restrict__ bv,
              __nv_bfloat16* __restrict__ qh, __nv_bfloat16* __restrict__ ql,
              __nv_bfloat16* __restrict__ kh, __nv_bfloat16* __restrict__ kl,
              __nv_bfloat16* __restrict__ vth, __nv_bfloat16* __restrict__ vtl)
{
    const int K = DIM;
#if TC_OK
    extern __shared__ char dynsmem[];
    __shared__ uint32_t sh_tmem;
    __shared__ __align__(8) uint64_t sh_full[WST];
    __shared__ __align__(8) uint64_t sh_empty[WST];

    const int tid = threadIdx.x;
    const int m0 = blockIdx.y * 128;
    const int n0 = blockIdx.x * 256;

    uint32_t sbase = smem_u32(dynsmem);
    sbase = (sbase + 1023u) & ~1023u;
    const uint32_t full_b = smem_u32(sh_full);
    const uint32_t empty_b = smem_u32(sh_empty);

    if (tid < 32) {
        tmem_alloc(smem_u32(&sh_tmem), 256);
        tmem_relinquish();
    }
    if (tid == 0) {
#pragma unroll
        for (int s = 0; s < WST; s++) {
            mbar_init(full_b + s * 8, 128);
            mbar_init(empty_b + s * 8, 1);
        }
    }
    __syncthreads();
    const uint32_t tmem = sh_tmem;

    wide_mainloop(sbase, tmem, full_b, empty_b, a_hi, a_lo, b_hi, b_lo, m0, n0, K, tid);

    if (tid < 128) {
        const int sel = n0 >> 10;                 // 0=Q, 1=K, 2=V (tile-constant)
        const int cbase = n0 & 1023;
        const float* bias = (sel == 0) ? bq : (sel == 1) ? bk : bv;
        if (sel < 2) {
            __nv_bfloat16* oh = sel ? kh : qh;
            __nv_bfloat16* ol = sel ? kl : ql;
            gemm_epilogue_cols<3>(tmem, m0, cbase, 256, tid, bias, nullptr,
                                  nullptr, oh, ol, DIM);
        } else {
            gemm_epilogue_cols<4>(tmem, m0, cbase, 256, tid, bias, nullptr,
                                  nullptr, vth, vtl, DIM);
        }
    }
    __syncthreads();
    if (tid < 32) tmem_dealloc(tmem, 256);

#else  // ===================== FFMA fallback ================================
    __shared__ float As[16][128];
    __shared__ float Bs[16][32];
    const int tid = threadIdx.x;
    const int m0 = blockIdx.y * 128;
    const int n0 = blockIdx.x * 256;
    const int row = m0 + (tid & 127);
    const int sel = n0 >> 10;
    const float* bias = (sel == 0) ? bq : (sel == 1) ? bk : bv;
    for (int p = 0; p < 8; p++) {
        const int c0 = n0 + p * 32;
        float acc[32];
#pragma unroll
        for (int j = 0; j < 32; j++) acc[j] = 0.f;
        for (int kt = 0; kt < K; kt += 16) {
            __syncthreads();
            for (int i = tid; i < 16 * 128; i += GTHREADS) {
                const int kk = i >> 7, r = i & 127;
                const size_t g = (size_t)(m0 + r) * K + kt + kk;
                As[kk][r] = __bfloat162float(a_hi[g]) + __bfloat162float(a_lo[g]);
            }
            for (int i = tid; i < 16 * 32; i += GTHREADS) {
                const int kk = i >> 5, r = i & 31;
                const size_t g = (size_t)(c0 + r) * K + kt + kk;
                Bs[kk][r] = __bfloat162float(b_hi[g]) + __bfloat162float(b_lo[g]);
            }
            __syncthreads();
            if (tid < 128) {
#pragma unroll
                for (int kk = 0; kk < 16; kk++) {
                    const float a = As[kk][tid];
#pragma unroll
                    for (int j = 0; j < 32; j++) acc[j] = fmaf(a, Bs[kk][j], acc[j]);
                }
            }
        }
        if (tid < 128) {
#pragma unroll
            for (int j = 0; j < 32; j++) {
                const int cg = c0 + j;              // global fused column
                const int c = cg & 1023;            // column within target
                float v = acc[j] + bias[c];
                __nv_bfloat16 h, l;
                bsplit(v, h, l);
                if (sel < 2) {
                    __nv_bfloat16* oh = sel ? kh : qh;
                    __nv_bfloat16* ol = sel ? kl : ql;
                    oh[(size_t)row * DIM + c] = h;
                    ol[(size_t)row * DIM + c] = l;
                } else {
                    const int b = row >> 11, s = row & 2047;
                    const size_t o = (((size_t)b * NHEAD + (c >> 6)) * HDIM + (c & 63)) * SEQ + s;
                    vth[o] = h;
                    vtl[o] = l;
                }
            }
        }
        __syncthreads();
    }
#endif
}

// ===== GEMM NARROW: warp-spec, 128x128 tiles, K-tile 32, 3 stages, occ 2 ===
#define NST       3
#define NSTAGE_B  (4 * AH_T)                 // 32768
#define GSMEM_N   (NST * NSTAGE_B + 1024)

template <int MODE>
__global__ __launch_bounds__(GTHREADS, 2)
void gemm_tcn(const __nv_bfloat16* __restrict__ a_hi, const __nv_bfloat16* __restrict__ a_lo,
              const __nv_bfloat16* __restrict__ b_hi, const __nv_bfloat16* __restrict__ b_lo,
              const float* __restrict__ bias, const float* __restrict__ res,
              float* __restrict__ out_f, __nv_bfloat16* __restrict__ out_hi,
              __nv_bfloat16* __restrict__ out_lo, int M, int N, int K)
{
#if TC_OK
    extern __shared__ char dynsmem[];
    __shared__ uint32_t sh_tmem;
    __shared__ __align__(8) uint64_t sh_full[NST];
    __shared__ __align__(8) uint64_t sh_empty[NST];

    const int tid = threadIdx.x;
    const int m0 = blockIdx.y * 128;
    const int n0 = blockIdx.x * 128;

    uint32_t sbase = smem_u32(dynsmem);
    sbase = (sbase + 1023u) & ~1023u;
    const uint32_t full_b = smem_u32(sh_full);
    const uint32_t empty_b = smem_u32(sh_empty);

    if (tid < 32) {
        tmem_alloc(smem_u32(&sh_tmem), 128);
        tmem_relinquish();
    }
    if (tid == 0) {
#pragma unroll
        for (int s = 0; s < NST; s++) {
            mbar_init(full_b + s * 8, 128);
            mbar_init(empty_b + s * 8, 1);
        }
    }
    __syncthreads();
    const uint32_t tmem = sh_tmem;
    const int T = K >> 5;

    constexpr uint32_t IDESC =
        (1u << 4) | (1u << 7) | (1u << 10) | ((128u / 8u) << 17) | ((128u / 16u) << 24);

    if (tid >= 32) {
        const int ltid = tid - 32;
        for (int lt = 0; lt < T; lt++) {
            const int s = lt % 3, pass = lt / 3;
            if (pass >= 1) mbar_wait(empty_b + s * 8, (uint32_t)((pass - 1) & 1));
            const uint32_t sdst = sbase + s * NSTAGE_B;
            const int kc = (lt << 5);
#pragma unroll
            for (int i = 0; i < 16; i++) {
                const int c = ltid + i * 128;
                const int idx = c & 511;
                const int row = idx >> 2, ch = idx & 3;
                const uint32_t off = (uint32_t)(row * 64 + ch * 16);
                const uint32_t sw = off ^ ((off >> 3) & 0x30);
                const int sel = c >> 9;
                const __nv_bfloat16* base =
                    (sel == 0) ? a_hi : (sel == 1) ? a_lo : (sel == 2) ? b_hi : b_lo;
                const int r0 = (sel < 2) ? m0 : n0;
                cpasync16(sdst + (uint32_t)sel * AH_T + sw,
                          base + (size_t)(r0 + row) * K + kc + ch * 8);
            }
            cp_mbar_arrive_noinc(full_b + s * 8);
        }
    } else if (elect_one()) {
        tc_fence_after();
        for (int kt = 0; kt < T; kt++) {
            const int s = kt % 3, pass = kt / 3;
            mbar_wait(full_b + s * 8, (uint32_t)(pass & 1));
            const uint32_t st = sbase + s * NSTAGE_B;
            const uint64_t dAhi = make_desc64(st);
            const uint64_t dAlo = make_desc64(st + AH_T);
            const uint64_t dBhi = make_desc64(st + 2 * AH_T);
            const uint64_t dBlo = make_desc64(st + 3 * AH_T);
#pragma unroll
            for (int ks = 0; ks < 2; ks++) {
                const uint32_t en = (kt > 0 || ks > 0) ? 1u : 0u;
                mma_f16_ss(tmem, dAhi + ks * 2, dBhi + ks * 2, IDESC, en);
                mma_f16_ss(tmem, dAlo + ks * 2, dBhi + ks * 2, IDESC, 1u);
                mma_f16_ss(tmem, dAhi + ks * 2, dBlo + ks * 2, IDESC, 1u);
            }
            tc_commit(empty_b + s * 8);
        }
    }

    {
        const int last = T - 1;
        mbar_wait(empty_b + (last % 3) * 8, (uint32_t)((last / 3) & 1));
    }
    __syncthreads();
    tc_fence_after();

    if (tid < 128)
        gemm_epilogue_cols<MODE>(tmem, m0, n0, 128, tid, bias, res, out_f, out_hi, out_lo, N);
    __syncthreads();
    if (tid < 32) tmem_dealloc(tmem, 128);

#else
    // FFMA fallback (correctness only)
    __shared__ float As[16][128];
    __shared__ float Bs[16][32];
    const int tid = threadIdx.x;
    const int m0 = blockIdx.y * 128;
    const int n0 = blockIdx.x * 128;
    const int row = m0 + (tid & 127);
    for (int p = 0; p < 4; p++) {
        const int c0 = n0 + p * 32;
        float acc[32];
#pragma unroll
        for (int j = 0; j < 32; j++) acc[j] = 0.f;
        for (int kt = 0; kt < K; kt += 16) {
            __syncthreads();
            for (int i = tid; i < 16 * 128; i += GTHREADS) {
                const int kk = i >> 7, r = i & 127;
                const size_t g = (size_t)(m0 + r) * K + kt + kk;
                As[kk][r] = __bfloat162float(a_hi[g]) + __bfloat162float(a_lo[g]);
            }
            for (int i = tid; i < 16 * 32; i += GTHREADS) {
                const int kk = i >> 5, r = i & 31;
                const size_t g = (size_t)(c0 + r) * K + kt + kk;
                Bs[kk][r] = __bfloat162float(b_hi[g]) + __bfloat162float(b_lo[g]);
            }
            __syncthreads();
            if (tid < 128) {
#pragma unroll
                for (int kk = 0; kk < 16; kk++) {
                    const float a = As[kk][tid];
#pragma unroll
                    for (int j = 0; j < 32; j++) acc[j] = fmaf(a, Bs[kk][j], acc[j]);
                }
            }
        }
        if (tid < 128) {
#pragma unroll
            for (int j = 0; j < 32; j++) {
                const int c = c0 + j;
                float v = acc[j] + bias[c];
                if (MODE == 1) {
                    out_f[(size_t)row * N + c] = v + res[(size_t)row * N + c];
                } else {
                    if (MODE == 2) v = gelu_f(v);
                    __nv_bfloat16 h, l;
                    bsplit(v, h, l);
                    out_hi[(size_t)row * N + c] = h;
                    out_lo[(size_t)row * N + c] = l;
                }
            }
        }
        __syncthreads();
    }
#endif
}

// ======================= tcgen05 flash attention ===========================
// O accumulates in TMEM across ALL K-tiles; drained once at the end.
#define AQ_OFF   0
#define AK_OFF(b) (32768 + (b) * 32768)
#define AV_OFF(b) (98304 + (b) * 32768)
#define AP_OFF   163840
#define ASM_TOTAL (229376 + 1024)

__global__ __launch_bounds__(128, 1)
void attn_tc(const __nv_bfloat16* __restrict__ qhi, const __nv_bfloat16* __restrict__ qlo,
             const __nv_bfloat16* __restrict__ khi, const __nv_bfloat16* __restrict__ klo,
             const __nv_bfloat16* __restrict__ vthi, const __nv_bfloat16* __restrict__ vtlo,
             __nv_bfloat16* __restrict__ ohi, __nv_bfloat16* __restrict__ olo)
{
#if TC_OK
    extern __shared__ char dyn[];
    __shared__ uint32_t sh_tmem;
    __shared__ __align__(8) uint64_t sh_mb[3];

    const int tid = threadIdx.x;
    const int qblk = blockIdx.x, bh = blockIdx.y;
    const int b = bh >> 4, h = bh & 15;
    const int T = SEQ / 128;

    uint32_t sb = smem_u32(dyn);
    sb = (sb + 1023u) & ~1023u;
    char* dynb = (char*)dyn + (sb - smem_u32(dyn));
    const uint32_t mb = smem_u32(sh_mb);
    const uint32_t qkmb0 = mb, qkmb1 = mb + 8, pvmb = mb + 16;

    if (tid < 32) {
        tmem_alloc(smem_u32(&sh_tmem), 512);
        tmem_relinquish();
    }
    if (tid == 0) { mbar_init(qkmb0, 1); mbar_init(qkmb1, 1); mbar_init(pvmb, 1); }
    __syncthreads();
    const uint32_t TMB = sh_tmem;

    const size_t koff0 = ((size_t)(b * SEQ)) * DIM + h * 64;
    const size_t voff0 = ((size_t)bh * 64) * SEQ;

    auto load_k = [&](int kt, int buf) {
        const uint32_t st = sb + AK_OFF(buf);
        const size_t koff = koff0 + (size_t)(kt * 128) * DIM;
        for (int c = tid; c < 2048; c += 128) {
            const int hl = c >> 10, r = (c >> 3) & 127, c16 = c & 7;
            const __nv_bfloat16* src = (hl ? klo : khi) + koff + (size_t)r * DIM + c16 * 8;
            uint32_t off = (uint32_t)(r * 128 + c16 * 16);
            off ^= (off >> 3) & 0x70;
            cpasync16(st + hl * 16384 + off, src);
        }
    };
    auto load_v = [&](int kt, int buf) {
        const uint32_t st = sb + AV_OFF(buf);
        const size_t voff = voff0 + kt * 128;
        for (int c = tid; c < 2048; c += 128) {
            const int tile = c >> 9, r = (c >> 3) & 63, c16 = c & 7;
            const int hl = tile >> 1, half = tile & 1;
            const __nv_bfloat16* src =
                (hl ? vtlo : vthi) + voff + (size_t)r * SEQ + half * 64 + c16 * 8;
            uint32_t off = (uint32_t)(r * 128 + c16 * 16);
            off ^= (off >> 3) & 0x70;
            cpasync16(st + tile * 8192 + off, src);
        }
    };

    constexpr uint32_t IDESC_QK =
        (1u << 4) | (1u << 7) | (1u << 10) | ((128u / 8u) << 17) | ((128u / 16u) << 24);
    constexpr uint32_t IDESC_PV =
        (1u << 4) | (1u << 7) | (1u << 10) | ((64u / 8u) << 17) | ((128u / 16u) << 24);

    const uint64_t dQhi = make_desc(sb + AQ_OFF), dQlo = make_desc(sb + AQ_OFF + 16384);

    auto issue_qk = [&](int kt) {
        const uint32_t sbuf = (uint32_t)(kt & 1);
        const uint32_t TS = TMB + sbuf * 128;
        const uint32_t st = sb + AK_OFF(kt & 1);
        const uint64_t dKhi = make_desc(st), dKlo = make_desc(st + 16384);
#pragma unroll
        for (int ks = 0; ks < 4; ks++)
            mma_f16_ss(TS, dQhi + ks * 2, dKhi + ks * 2, IDESC_QK, ks > 0 ? 1u : 0u);
#pragma unroll
        for (int ks = 0; ks < 4; ks++)
            mma_f16_ss(TS, dQlo + ks * 2, dKhi + ks * 2, IDESC_QK, 1u);
#pragma unroll
        for (int ks = 0; ks < 4; ks++)
            mma_f16_ss(TS, dQhi + ks * 2, dKlo + ks * 2, IDESC_QK, 1u);
        tc_commit((kt & 1) ? qkmb1 : qkmb0);
    };

    // prologue: Q + K0 (g0), K1 (g1), V0 (g2)
    {
        const size_t qoff = ((size_t)(b * SEQ + qblk * 128)) * DIM + h * 64;
        for (int c = tid; c < 2048; c += 128) {
            const int hl = c >> 10, r = (c >> 3) & 127, c16 = c & 7;
            const __nv_bfloat16* src = (hl ? qlo : qhi) + qoff + (size_t)r * DIM + c16 * 8;
            uint32_t off = (uint32_t)(r * 128 + c16 * 16);
            off ^= (off >> 3) & 0x70;
            cpasync16(sb + AQ_OFF + (hl ? 16384 : 0) + off, src);
        }
        load_k(0, 0);
        cp_commit();
        load_k(1, 1);
        cp_commit();
        load_v(0, 0);
        cp_commit();
    }
    cp_wait2();
    fence_proxy_async_shared();
    __syncthreads();
    if (tid < 32 && elect_one()) {
        tc_fence_after();
        issue_qk(0);
    }

    float l = 0.f;

    for (int kt = 0; kt < T; kt++) {
        const int sbuf = kt & 1;
        const uint32_t TS = TMB + sbuf * 128;
        const uint32_t TO = TMB + 256;

        mbar_wait(sbuf ? qkmb1 : qkmb0, (uint32_t)((kt >> 1) & 1));
        tc_fence_after();

        cp_wait1();
        fence_proxy_async_shared();
        __syncthreads();
        if (kt + 1 < T) {
            if (tid < 32 && elect_one()) {
                tc_fence_after();
                issue_qk(kt + 1);
            }
        }

        if (kt + 2 < T) load_k(kt + 2, sbuf);
        cp_commit();

        if (kt >= 1) mbar_wait(pvmb, (uint32_t)((kt - 1) & 1));
        if (kt + 1 < T) load_v(kt + 1, (kt + 1) & 1);
        cp_commit();

#pragma unroll
        for (int c0 = 0; c0 < 128; c0 += 32) {
            uint32_t sr[32];
            tmem_ld32(sr, TS + c0);
            tmem_wait_ld();
            float p[32];
#pragma unroll
            for (int j = 0; j < 32; j++) {
                p[j] = __expf(__uint_as_float(sr[j]) * 0.125f);
                l += p[j];
            }
            const int hsel = (c0 >= 64);
            const int cb = (c0 & 63) * 2;
#pragma unroll
            for (int g = 0; g < 4; g++) {
                ushort hs[8], ls[8];
#pragma unroll
                for (int e = 0; e < 8; e++) {
                    __nv_bfloat16 hb, lb;
                    bsplit(p[g * 8 + e], hb, lb);
                    hs[e] = __bfloat16_as_ushort(hb);
                    ls[e] = __bfloat16_as_ushort(lb);
                }
                uint32_t off = (uint32_t)(tid * 128 + cb + g * 16);
                off ^= (off >> 3) & 0x70;
                *(uint4*)(dynb + AP_OFF + hsel * 16384 + off) = *(uint4*)hs;
                *(uint4*)(dynb + AP_OFF + 32768 + hsel * 16384 + off) = *(uint4*)ls;
            }
        }
        tc_fence_before();

        asm volatile("cp.async.wait_group 2;" ::: "memory");
        fence_proxy_async_shared();
        __syncthreads();
        if (tid < 32 && elect_one()) {
            tc_fence_after();
            const uint32_t vst = sb + AV_OFF(sbuf);
            int first = (kt == 0);
#pragma unroll
            for (int half = 0; half < 2; half++) {
                const uint64_t dPh = make_desc(sb + AP_OFF + half * 16384);
                const uint64_t dPl = make_desc(sb + AP_OFF + 32768 + half * 16384);
                const uint64_t dVh = make_desc(vst + half * 8192);
                const uint64_t dVl = make_desc(vst + (2 + half) * 8192);
#pragma unroll
                for (int ks = 0; ks < 4; ks++) {
                    mma_f16_ss(TO, dPh + ks * 2, dVh + ks * 2, IDESC_PV, first ? 0u : 1u);
                    first = 0;
                    mma_f16_ss(TO, dPl + ks * 2, dVh + ks * 2, IDESC_PV, 1u);
                    mma_f16_ss(TO, dPh + ks * 2, dVl + ks * 2, IDESC_PV, 1u);
                }
            }
            tc_commit(pvmb);
        }
    }

    mbar_wait(pvmb, (uint32_t)((T - 1) & 1));
    tc_fence_after();

    const float inv = 1.0f / l;
    const size_t obase = ((size_t)(b * SEQ + qblk * 128 + tid)) * DIM + h * 64;
#pragma unroll
    for (int c0 = 0; c0 < 64; c0 += 32) {
        uint32_t pr[32];
        tmem_ld32(pr, TMB + 256 + c0);
        tmem_wait_ld();
#pragma unroll
        for (int j0 = 0; j0 < 32; j0 += 4) {
            ushort hs[4], ls[4];
#pragma unroll
            for (int jj = 0; jj < 4; jj++) {
                __nv_bfloat16 hb, lb;
                bsplit(__uint_as_float(pr[j0 + jj]) * inv, hb, lb);
                hs[jj] = __bfloat16_as_ushort(hb);
                ls[jj] = __bfloat16_as_ushort(lb);
            }
            *(ushort4*)(ohi + obase + c0 + j0) = make_ushort4(hs[0], hs[1], hs[2], hs[3]);
            *(ushort4*)(olo + obase + c0 + j0) = make_ushort4(ls[0], ls[1], ls[2], ls[3]);
        }
    }
    tc_fence_before();
    __syncthreads();
    if (tid < 32) tmem_dealloc(sh_tmem, 512);

#else  // fallback fp32 attention
    const int bh = blockIdx.y;
    const int b = bh >> 4;
    const int qrow = blockIdx.x * 128 + threadIdx.x;
    const size_t qkbase = ((size_t)b * SEQ) * DIM + (size_t)(bh & 15) * HDIM;
    const size_t vbase = ((size_t)bh * HDIM) * SEQ;

    float q[HDIM];
    {
        const __nv_bfloat16* qph = qhi + qkbase + (size_t)qrow * DIM;
        const __nv_bfloat16* qpl = qlo + qkbase + (size_t)qrow * DIM;
#pragma unroll
        for (int d = 0; d < HDIM; d++)
            q[d] = __bfloat162float(qph[d]) + __bfloat162float(qpl[d]);
    }
    float o[HDIM];
#pragma unroll
    for (int d = 0; d < HDIM; d++) o[d] = 0.f;
    float l = 0.f;

    __shared__ float Ks[32][HDIM];
    __shared__ float Vs[32][HDIM];

    for (int kt = 0; kt < SEQ / 32; kt++) {
        __syncthreads();
        const int kbase = kt * 32;
        for (int i = threadIdx.x; i < 32 * HDIM; i += 128) {
            const int j = i >> 6, d = i & 63;
            const size_t g = qkbase + (size_t)(kbase + j) * DIM + d;
            Ks[j][d] = __bfloat162float(khi[g]) + __bfloat162float(klo[g]);
            const size_t gv = vbase + (size_t)d * SEQ + kbase + j;
            Vs[j][d] = __bfloat162float(vthi[gv]) + __bfloat162float(vtlo[gv]);
        }
        __syncthreads();

#pragma unroll
        for (int j = 0; j < 32; j++) {
            float s = 0.f;
#pragma unroll
            for (int d = 0; d < HDIM; d++) s = fmaf(q[d], Ks[j][d], s);
            const float p = __expf(s * 0.125f);
            l += p;
#pragma unroll
            for (int d = 0; d < HDIM; d++) o[d] = fmaf(p, Vs[j][d], o[d]);
        }
    }

    const float inv = 1.0f / l;
    const size_t ob = qkbase + (size_t)qrow * DIM;
#pragma unroll
    for (int d = 0; d < HDIM; d++) {
        __nv_bfloat16 hb, lb;
        bsplit(o[d] * inv, hb, lb);
        ohi[ob + d] = hb;
        olo[ob + d] = lb;
    }
#endif
}

// ======================= launch ============================================
extern "C" void kernel_launch(void* const* d_in, const int* in_sizes, int n_in,
                              void* d_out, int out_size)
{
    const float* feature = (const float*)d_in[0];
    const float* wq = (const float*)d_in[2];
    const float* bq = (const float*)d_in[3];
    const float* wk = (const float*)d_in[4];
    const float* bk = (const float*)d_in[5];
    const float* wv = (const float*)d_in[6];
    const float* bv = (const float*)d_in[7];
    const float* wo = (const float*)d_in[8];
    const float* bo = (const float*)d_in[9];
    const float* ln1g = (const float*)d_in[10];
    const float* ln1b = (const float*)d_in[11];
    const float* ln2g = (const float*)d_in[12];
    const float* ln2b = (const float*)d_in[13];
    const float* w1 = (const float*)d_in[14];
    const float* b1 = (const float*)d_in[15];
    const float* w2 = (const float*)d_in[16];
    const float* b2 = (const float*)d_in[17];
    float* out = (float*)d_out;

    __nv_bfloat16 *xln1h, *xln1l, *attnh, *attnl, *xln2h, *xln2l, *h1h, *h1l;
    __nv_bfloat16 *qh, *ql, *kh, *kl, *vth, *vtl;
    __nv_bfloat16 *wqkvh, *wqkvl, *woh, *wol, *w1h, *w1l, *w2h, *w2l;
    float *feat;
    cudaGetSymbolAddress((void**)&xln1h, g_xln1_hi);
    cudaGetSymbolAddress((void**)&xln1l, g_xln1_lo);
    cudaGetSymbolAddress((void**)&qh, g_q_hi);  cudaGetSymbolAddress((void**)&ql, g_q_lo);
    cudaGetSymbolAddress((void**)&kh, g_k_hi);  cudaGetSymbolAddress((void**)&kl, g_k_lo);
    cudaGetSymbolAddress((void**)&vth, g_vt_hi); cudaGetSymbolAddress((void**)&vtl, g_vt_lo);
    cudaGetSymbolAddress((void**)&attnh, g_attn_hi);
    cudaGetSymbolAddress((void**)&attnl, g_attn_lo);
    cudaGetSymbolAddress((void**)&feat, g_feat);
    cudaGetSymbolAddress((void**)&xln2h, g_xln2_hi);
    cudaGetSymbolAddress((void**)&xln2l, g_xln2_lo);
    cudaGetSymbolAddress((void**)&h1h, g_h1_hi);
    cudaGetSymbolAddress((void**)&h1l, g_h1_lo);
    cudaGetSymbolAddress((void**)&wqkvh, g_wqkvT_hi);
    cudaGetSymbolAddress((void**)&wqkvl, g_wqkvT_lo);
    cudaGetSymbolAddress((void**)&woh, g_woT_hi); cudaGetSymbolAddress((void**)&wol, g_woT_lo);
    cudaGetSymbolAddress((void**)&w1h, g_w1T_hi); cudaGetSymbolAddress((void**)&w1l, g_w1T_lo);
    cudaGetSymbolAddress((void**)&w2h, g_w2T_hi); cudaGetSymbolAddress((void**)&w2l, g_w2T_lo);

    cudaFuncSetAttribute(gemm_qkv, cudaFuncAttributeMaxDynamicSharedMemorySize, GSMEM_W);
    cudaFuncSetAttribute(gemm_tcw<1>, cudaFuncAttributeMaxDynamicSharedMemorySize, GSMEM_W);
    cudaFuncSetAttribute(gemm_tcn<1>, cudaFuncAttributeMaxDynamicSharedMemorySize, GSMEM_N);
    cudaFuncSetAttribute(gemm_tcn<2>, cudaFuncAttributeMaxDynamicSharedMemorySize, GSMEM_N);
    cudaFuncSetAttribute(attn_tc, cudaFuncAttributeMaxDynamicSharedMemorySize, ASM_TOTAL);

    // all weight conversions in ONE launch (QKV into fused buffer)
    wtrans_all<<<12288, 256>>>(wq, wk, wv, wo, w1, w2,
                               wqkvh, wqkvl, woh, wol, w1h, w1l, w2h, w2l);

    // LN1
    ln_kernel<<<NTOK, 256>>>(feature, ln1g, ln1b, xln1h, xln1l);

    // FUSED QKV: one wide GEMM, N=3072, per-tile output routing
    gemm_qkv<<<dim3(3 * DIM / 256, NTOK / 128), GTHREADS, GSMEM_W>>>(
        xln1h, xln1l, wqkvh, wqkvl, bq, bk, bv, qh, ql, kh, kl, vth, vtl);

    // attention (tcgen05 flash, O accumulated in TMEM)
    attn_tc<<<dim3(SEQ / 128, Bz * NHEAD), 128, ASM_TOTAL>>>(qh, ql, kh, kl, vth, vtl,
                                                             attnh, attnl);

    // O projection + residual(feature): WIDE
    gemm_tcw<1><<<dim3(DIM / 256, NTOK / 128), GTHREADS, GSMEM_W>>>(
        attnh, attnl, woh, wol, bo, feature, feat, nullptr, nullptr, NTOK, DIM, DIM);

    // LN2
    ln_kernel<<<NTOK, 256>>>(feat, ln2g, ln2b, xln2h, xln2l);

    // FFN up + GELU: NARROW (multi-wave; R12 evidence)
    gemm_tcn<2><<<dim3(FF / 128, NTOK / 128), GTHREADS, GSMEM_N>>>(
        xln2h, xln2l, w1h, w1l, b1, nullptr, nullptr, h1h, h1l, NTOK, FF, DIM);

    // FFN down + residual(feat) -> out: NARROW
    gemm_tcn<1><<<dim3(DIM / 128, NTOK / 128), GTHREADS, GSMEM_N>>>(
        h1h, h1l, w2h, w2l, b2, feat, out, nullptr, nullptr, NTOK, DIM, FF);
}

// round 15
// speedup vs baseline: 7.3349x; 1.0872x over previous
#include <cuda_runtime.h>
#include <cuda_bf16.h>
#include <math.h>
#include <stdint.h>

// Problem constants
#define Bz    2
#define SEQ   2048
#define DIM   1024
#define NHEAD 16
#define HDIM  64
#define FF    4096
#define NTOK  (Bz * SEQ)   // 4096

// tcgen05 availability for THIS compilation pass (arch- or family-specific >= sm_100)
#if defined(__CUDA_ARCH_FEAT_SM103_ALL) || defined(__CUDA_ARCH_FEAT_SM100_ALL) || \
    defined(__CUDA_ARCH_FEAT_SM101_ALL) ||                                        \
    (defined(__CUDA_ARCH_SPECIFIC__) && (__CUDA_ARCH_SPECIFIC__ >= 1000)) ||       \
    (defined(__CUDA_ARCH_FAMILY_SPECIFIC__) && (__CUDA_ARCH_FAMILY_SPECIFIC__ >= 1000))
#define TC_OK 1
#else
#define TC_OK 0
#endif

// ======================= scratch (device globals) ==========================
__device__ __align__(16) __nv_bfloat16 g_xln1_hi[NTOK * DIM];
__device__ __align__(16) __nv_bfloat16 g_xln1_lo[NTOK * DIM];
__device__ __align__(16) __nv_bfloat16 g_q_hi[NTOK * DIM], g_q_lo[NTOK * DIM];
__device__ __align__(16) __nv_bfloat16 g_k_hi[NTOK * DIM], g_k_lo[NTOK * DIM];
__device__ __align__(16) __nv_bfloat16 g_vt_hi[NTOK * DIM], g_vt_lo[NTOK * DIM]; // [b,h,hd,s]
__device__ __align__(16) __nv_bfloat16 g_attn_hi[NTOK * DIM];
__device__ __align__(16) __nv_bfloat16 g_attn_lo[NTOK * DIM];
__device__ __align__(16) float         g_feat[NTOK * DIM];
__device__ __align__(16) __nv_bfloat16 g_xln2_hi[NTOK * DIM];
__device__ __align__(16) __nv_bfloat16 g_xln2_lo[NTOK * DIM];
__device__ __align__(16) __nv_bfloat16 g_h1_hi[NTOK * FF];
__device__ __align__(16) __nv_bfloat16 g_h1_lo[NTOK * FF];
// transposed bf16 weights [N,K]; QKV fused: rows 0-1023 Q, 1024-2047 K, 2048-3071 V
__device__ __align__(16) __nv_bfloat16 g_wqkvT_hi[3 * DIM * DIM], g_wqkvT_lo[3 * DIM * DIM];
__device__ __align__(16) __nv_bfloat16 g_woT_hi[DIM * DIM], g_woT_lo[DIM * DIM];
__device__ __align__(16) __nv_bfloat16 g_w1T_hi[DIM * FF],  g_w1T_lo[DIM * FF];
__device__ __align__(16) __nv_bfloat16 g_w2T_hi[FF * DIM],  g_w2T_lo[FF * DIM];

// ======================= common helpers ====================================
__device__ __forceinline__ void bsplit(float v, __nv_bfloat16& h, __nv_bfloat16& l) {
    h = __float2bfloat16_rn(v);
    l = __float2bfloat16_rn(v - __bfloat162float(h));
}
__device__ __forceinline__ float gelu_f(float x) {
    return 0.5f * x * (1.0f + erff(x * 0.70710678118654752f));
}

#if TC_OK
// ======================= tcgen05 PTX helpers (sm_103a pass only) ===========
__device__ __forceinline__ uint32_t smem_u32(const void* p) {
    uint32_t a;
    asm("{ .reg .u64 t; cvta.to.shared.u64 t, %1; cvt.u32.u64 %0, t; }"
        : "=r"(a) : "l"(p));
    return a;
}
__device__ __forceinline__ uint32_t elect_one() {
    uint32_t pred;
    asm volatile("{\n\t.reg .pred p;\n\telect.sync _|p, 0xFFFFFFFF;\n\t"
                 "selp.b32 %0, 1, 0, p;\n\t}" : "=r"(pred));
    return pred;
}
__device__ __forceinline__ void mbar_init(uint32_t mbar, uint32_t cnt) {
    asm volatile("mbarrier.init.shared.b64 [%0], %1;" :: "r"(mbar), "r"(cnt) : "memory");
}
__device__ __forceinline__ void mbar_wait(uint32_t mbar, uint32_t parity) {
    asm volatile(
        "{\n\t.reg .pred P1;\n\t"
        "WAIT_LOOP_%=:\n\t"
        "mbarrier.try_wait.parity.acquire.cta.shared::cta.b64 P1, [%0], %1, 0x989680;\n\t"
        "@P1 bra.uni WAIT_DONE_%=;\n\t"
        "bra.uni WAIT_LOOP_%=;\n\t"
        "WAIT_DONE_%=:\n\t}"
        :: "r"(mbar), "r"(parity) : "memory");
}
// .noinc: arrival counts against the barrier's initialized expected count.
__device__ __forceinline__ void cp_mbar_arrive_noinc(uint32_t mbar) {
    asm volatile("cp.async.mbarrier.arrive.noinc.shared::cta.b64 [%0];"
                 :: "r"(mbar) : "memory");
}
__device__ __forceinline__ void tmem_alloc(uint32_t dst_smem, uint32_t ncols) {
    asm volatile("tcgen05.alloc.cta_group::1.sync.aligned.shared::cta.b32 [%0], %1;"
                 :: "r"(dst_smem), "r"(ncols) : "memory");
}
__device__ __forceinline__ void tmem_dealloc(uint32_t tmem, uint32_t ncols) {
    asm volatile("tcgen05.dealloc.cta_group::1.sync.aligned.b32 %0, %1;"
                 :: "r"(tmem), "r"(ncols));
}
__device__ __forceinline__ void tmem_relinquish() {
    asm volatile("tcgen05.relinquish_alloc_permit.cta_group::1.sync.aligned;");
}
__device__ __forceinline__ void tc_commit(uint32_t mbar) {
    asm volatile("tcgen05.commit.cta_group::1.mbarrier::arrive::one.shared::cluster.b64 [%0];"
                 :: "r"(mbar) : "memory");
}
__device__ __forceinline__ void tc_fence_after() {
    asm volatile("tcgen05.fence::after_thread_sync;" ::: "memory");
}
__device__ __forceinline__ void tc_fence_before() {
    asm volatile("tcgen05.fence::before_thread_sync;" ::: "memory");
}
__device__ __forceinline__ void fence_proxy_async_shared() {
    asm volatile("fence.proxy.async.shared::cta;" ::: "memory");
}
__device__ __forceinline__ void mma_f16_ss(uint32_t d, uint64_t ad, uint64_t bd,
                                           uint32_t idesc, uint32_t en) {
    asm volatile(
        "{\n\t.reg .pred p;\n\tsetp.ne.u32 p, %5, 0;\n\t"
        "tcgen05.mma.cta_group::1.kind::f16 [%0], %1, %2, %3, {%4, %4, %4, %4}, p;\n\t}"
        :: "r"(d), "l"(ad), "l"(bd), "r"(idesc), "r"(0u), "r"(en) : "memory");
}
__device__ __forceinline__ void tmem_ld32(uint32_t* r, uint32_t addr) {
    asm volatile(
        "tcgen05.ld.sync.aligned.32x32b.x32.b32 "
        "{%0, %1, %2, %3, %4, %5, %6, %7, "
        " %8, %9, %10, %11, %12, %13, %14, %15, "
        " %16, %17, %18, %19, %20, %21, %22, %23, "
        " %24, %25, %26, %27, %28, %29, %30, %31}, [%32];"
        : "=r"(r[0]), "=r"(r[1]), "=r"(r[2]), "=r"(r[3]),
          "=r"(r[4]), "=r"(r[5]), "=r"(r[6]), "=r"(r[7]),
          "=r"(r[8]), "=r"(r[9]), "=r"(r[10]), "=r"(r[11]),
          "=r"(r[12]), "=r"(r[13]), "=r"(r[14]), "=r"(r[15]),
          "=r"(r[16]), "=r"(r[17]), "=r"(r[18]), "=r"(r[19]),
          "=r"(r[20]), "=r"(r[21]), "=r"(r[22]), "=r"(r[23]),
          "=r"(r[24]), "=r"(r[25]), "=r"(r[26]), "=r"(r[27]),
          "=r"(r[28]), "=r"(r[29]), "=r"(r[30]), "=r"(r[31])
        : "r"(addr));
}
__device__ __forceinline__ void tmem_wait_ld() {
    asm volatile("tcgen05.wait::ld.sync.aligned;" ::: "memory");
}
__device__ __forceinline__ void cpasync16(uint32_t dst, const void* src) {
    asm volatile("cp.async.cg.shared.global [%0], [%1], 16;" :: "r"(dst), "l"(src));
}
__device__ __forceinline__ void cp_commit() {
    asm volatile("cp.async.commit_group;" ::: "memory");
}
__device__ __forceinline__ void cp_wait1() {
    asm volatile("cp.async.wait_group 1;" ::: "memory");
}
__device__ __forceinline__ void cp_wait2() {
    asm volatile("cp.async.wait_group 2;" ::: "memory");
}
// SW128 SMEM descriptor (128B rows): layout 2, version 1, SBO=64, LBO=1
__device__ __forceinline__ uint64_t make_desc(uint32_t addr) {
    const uint64_t base =
        (uint64_t(2) << 61) | (uint64_t(1) << 46) | (uint64_t(64) << 32) | (uint64_t(1) << 16);
    return base | ((uint64_t)(addr >> 4) & 0x3FFF);
}
// SW64 SMEM descriptor (64B rows): layout 4, version 1, SBO=32, LBO=1
__device__ __forceinline__ uint64_t make_desc64(uint32_t addr) {
    const uint64_t base =
        (uint64_t(4) << 61) | (uint64_t(1) << 46) | (uint64_t(32) << 32) | (uint64_t(1) << 16);
    return base | ((uint64_t)(addr >> 4) & 0x3FFF);
}
#endif  // TC_OK

// ======================= LayerNorm -> bf16 hi/lo ===========================
__global__ __launch_bounds__(256)
void ln_kernel(const float* __restrict__ x, const float* __restrict__ g,
               const float* __restrict__ b,
               __nv_bfloat16* __restrict__ y_hi, __nv_bfloat16* __restrict__ y_lo)
{
    const int row = blockIdx.x;
    const int t = threadIdx.x;
    const float4 v = ((const float4*)(x + (size_t)row * DIM))[t];

    float s = v.x + v.y + v.z + v.w;
    __shared__ float sh[8];
#pragma unroll
    for (int o = 16; o > 0; o >>= 1) s += __shfl_xor_sync(0xffffffffu, s, o);
    if ((t & 31) == 0) sh[t >> 5] = s;
    __syncthreads();
    float tot = 0.f;
#pragma unroll
    for (int i = 0; i < 8; i++) tot += sh[i];
    const float mu = tot * (1.0f / DIM);

    const float dx = v.x - mu, dy = v.y - mu, dz = v.z - mu, dw = v.w - mu;
    float sq = dx * dx + dy * dy + dz * dz + dw * dw;
#pragma unroll
    for (int o = 16; o > 0; o >>= 1) sq += __shfl_xor_sync(0xffffffffu, sq, o);
    __syncthreads();
    if ((t & 31) == 0) sh[t >> 5] = sq;
    __syncthreads();
    float v2 = 0.f;
#pragma unroll
    for (int i = 0; i < 8; i++) v2 += sh[i];
    const float rstd = rsqrtf(v2 * (1.0f / DIM) + 1e-5f);

    const float4 gg = ((const float4*)g)[t];
    const float4 bb = ((const float4*)b)[t];
    float o0 = dx * rstd * gg.x + bb.x;
    float o1 = dy * rstd * gg.y + bb.y;
    float o2 = dz * rstd * gg.z + bb.z;
    float o3 = dw * rstd * gg.w + bb.w;

    __nv_bfloat16 h0, h1, h2, h3, l0, l1, l2, l3;
    bsplit(o0, h0, l0); bsplit(o1, h1, l1); bsplit(o2, h2, l2); bsplit(o3, h3, l3);
    ((ushort4*)(y_hi + (size_t)row * DIM))[t] =
        make_ushort4(__bfloat16_as_ushort(h0), __bfloat16_as_ushort(h1),
                     __bfloat16_as_ushort(h2), __bfloat16_as_ushort(h3));
    ((ushort4*)(y_lo + (size_t)row * DIM))[t] =
        make_ushort4(__bfloat16_as_ushort(l0), __bfloat16_as_ushort(l1),
                     __bfloat16_as_ushort(l2), __bfloat16_as_ushort(l3));
}

// ============ fused weight transpose + bf16 split (all 6 weights) ==========
__global__ __launch_bounds__(256)
void wtrans_all(const float* __restrict__ wq, const float* __restrict__ wk,
                const float* __restrict__ wv, const float* __restrict__ wo,
                const float* __restrict__ w1, const float* __restrict__ w2,
                __nv_bfloat16* qkvh, __nv_bfloat16* qkvl,
                __nv_bfloat16* oh, __nv_bfloat16* ol,
                __nv_bfloat16* f1h, __nv_bfloat16* f1l,
                __nv_bfloat16* f2h, __nv_bfloat16* f2l)
{
    int id = blockIdx.x;
    const float* W;
    __nv_bfloat16 *bh, *bl;
    int K, N;
    if (id < 4096) {
        const int s = id >> 10;
        id &= 1023;
        K = DIM; N = DIM;
        W  = (s == 0) ? wq : (s == 1) ? wk : (s == 2) ? wv : wo;
        if (s < 3) { bh = qkvh + (size_t)s * DIM * DIM; bl = qkvl + (size_t)s * DIM * DIM; }
        else       { bh = oh; bl = ol; }
    } else if (id < 8192) {
        id -= 4096; W = w1; K = DIM; N = FF; bh = f1h; bl = f1l;
    } else {
        id -= 8192; W = w2; K = FF; N = DIM; bh = f2h; bl = f2l;
    }
    const int nx = N / 32;
    const int n0 = (id % nx) * 32, k0 = (id / nx) * 32;

    __shared__ float t[32][33];
    const int tx = threadIdx.x & 31, ty = threadIdx.x >> 5;
#pragma unroll
    for (int i = 0; i < 4; i++) {
        const int r = ty + i * 8;
        t[r][tx] = W[(size_t)(k0 + r) * N + n0 + tx];
    }
    __syncthreads();
#pragma unroll
    for (int i = 0; i < 4; i++) {
        const int r = ty + i * 8;
        const float v = t[tx][r];
        __nv_bfloat16 h, l;
        bsplit(v, h, l);
        const size_t o = (size_t)(n0 + r) * K + k0 + tx;
        bh[o] = h;
        bl[o] = l;
    }
}

// ======================= shared epilogue helper ============================
#if TC_OK
template <int MODE>
__device__ __forceinline__ void gemm_epilogue_cols(
    uint32_t tmem, int m0, int n0, int ncols, int tid,
    const float* __restrict__ bias, const float* __restrict__ res,
    float* __restrict__ out_f, __nv_bfloat16* __restrict__ out_hi,
    __nv_bfloat16* __restrict__ out_lo, int N)
{
    const int w = tid >> 5, lane = tid & 31;
    const int row = m0 + w * 32 + lane;
    for (int c0 = 0; c0 < ncols; c0 += 32) {
        uint32_t dreg[32];
        tmem_ld32(dreg, tmem + c0);
        tmem_wait_ld();
        const int colbase = n0 + c0;
        if (MODE == 2 || MODE == 3) {
#pragma unroll
            for (int j0 = 0; j0 < 32; j0 += 8) {
                ushort hs[8], ls[8];
#pragma unroll
                for (int jj = 0; jj < 8; jj++) {
                    float v = __uint_as_float(dreg[j0 + jj]) + bias[colbase + j0 + jj];
                    if (MODE == 2) v = gelu_f(v);
                    __nv_bfloat16 h, l;
                    bsplit(v, h, l);
                    hs[jj] = __bfloat16_as_ushort(h);
                    ls[jj] = __bfloat16_as_ushort(l);
                }
                const size_t o = (size_t)row * N + colbase + j0;
                *(ushort4*)(out_hi + o)     = make_ushort4(hs[0], hs[1], hs[2], hs[3]);
                *(ushort4*)(out_hi + o + 4) = make_ushort4(hs[4], hs[5], hs[6], hs[7]);
                *(ushort4*)(out_lo + o)     = make_ushort4(ls[0], ls[1], ls[2], ls[3]);
                *(ushort4*)(out_lo + o + 4) = make_ushort4(ls[4], ls[5], ls[6], ls[7]);
            }
        } else if (MODE == 4) {
            const int b = row >> 11, s = row & 2047;
#pragma unroll
            for (int jj = 0; jj < 32; jj++) {
                const int c = colbase + jj;
                float v = __uint_as_float(dreg[jj]) + bias[c];
                __nv_bfloat16 h, l;
                bsplit(v, h, l);
                const size_t o = (((size_t)b * NHEAD + (c >> 6)) * HDIM + (c & 63)) * SEQ + s;
                out_hi[o] = h;
                out_lo[o] = l;
            }
        } else {  // MODE 1
            float* op = out_f + (size_t)row * N + colbase;
            const float* rp = res + (size_t)row * N + colbase;
#pragma unroll
            for (int j0 = 0; j0 < 32; j0 += 4) {
                float4 ov;
                ov.x = __uint_as_float(dreg[j0 + 0]) + bias[colbase + j0 + 0];
                ov.y = __uint_as_float(dreg[j0 + 1]) + bias[colbase + j0 + 1];
                ov.z = __uint_as_float(dreg[j0 + 2]) + bias[colbase + j0 + 2];
                ov.w = __uint_as_float(dreg[j0 + 3]) + bias[colbase + j0 + 3];
                const float4 rv = *(const float4*)(rp + j0);
                ov.x += rv.x; ov.y += rv.y; ov.z += rv.z; ov.w += rv.w;
                *(float4*)(op + j0) = ov;
            }
        }
    }
    tc_fence_before();
}
#endif

// ======================= wide GEMM mainloop (shared) =======================
#define WST       4
#define AH_T      8192
#define BH_T      16384
#define WSTAGE_B  (2 * AH_T + 2 * BH_T)      // 49152
#define GSMEM_W   (WST * WSTAGE_B + 1024)
#define GTHREADS  160

#if TC_OK
__device__ __forceinline__ void wide_mainloop(
    uint32_t sbase, uint32_t tmem, uint32_t full_b, uint32_t empty_b,
    const __nv_bfloat16* a_hi, const __nv_bfloat16* a_lo,
    const __nv_bfloat16* b_hi, const __nv_bfloat16* b_lo,
    int m0, int n0, int K, int tid)
{
    const int T = K >> 5;
    constexpr uint32_t IDESC =
        (1u << 4) | (1u << 7) | (1u << 10) | ((128u / 8u) << 17) | ((128u / 16u) << 24);

    if (tid >= 32) {
        const int ltid = tid - 32;
        for (int lt = 0; lt < T; lt++) {
            const int s = lt & 3, pass = lt >> 2;
            if (pass >= 1) mbar_wait(empty_b + s * 8, (uint32_t)((pass - 1) & 1));
            const uint32_t sdst = sbase + s * WSTAGE_B;
            const int kc = (lt << 5);
#pragma unroll
            for (int i = 0; i < 24; i++) {
                const int c = ltid + i * 128;
                const __nv_bfloat16* srcp;
                uint32_t dst;
                if (c < 1024) {
                    const int idx = c & 511;
                    const int row = idx >> 2, ch = idx & 3;
                    const uint32_t off = (uint32_t)(row * 64 + ch * 16);
                    const uint32_t sw = off ^ ((off >> 3) & 0x30);
                    srcp = ((c < 512) ? a_hi : a_lo) + (size_t)(m0 + row) * K + kc + ch * 8;
                    dst = sdst + ((c < 512) ? 0u : (uint32_t)AH_T) + sw;
                } else {
                    const int idx = c & 1023;
                    const int row = idx >> 2, ch = idx & 3;
                    const uint32_t off = (uint32_t)(row * 64 + ch * 16);
                    const uint32_t sw = off ^ ((off >> 3) & 0x30);
                    srcp = ((c < 2048) ? b_hi : b_lo) + (size_t)(n0 + row) * K + kc + ch * 8;
                    dst = sdst + ((c < 2048) ? (uint32_t)(2 * AH_T)
                                             : (uint32_t)(2 * AH_T + BH_T)) + sw;
                }
                cpasync16(dst, srcp);
            }
            cp_mbar_arrive_noinc(full_b + s * 8);
        }
    } else if (elect_one()) {
        tc_fence_after();
        for (int kt = 0; kt < T; kt++) {
            const int s = kt & 3, pass = kt >> 2;
            mbar_wait(full_b + s * 8, (uint32_t)(pass & 1));
            const uint32_t st = sbase + s * WSTAGE_B;
            const uint64_t dAhi = make_desc64(st);
            const uint64_t dAlo = make_desc64(st + AH_T);
            const uint64_t dB0hi = make_desc64(st + 2 * AH_T);
            const uint64_t dB1hi = make_desc64(st + 2 * AH_T + 8192);
            const uint64_t dB0lo = make_desc64(st + 2 * AH_T + BH_T);
            const uint64_t dB1lo = make_desc64(st + 2 * AH_T + BH_T + 8192);
#pragma unroll
            for (int ks = 0; ks < 2; ks++) {
                const uint32_t en = (kt > 0 || ks > 0) ? 1u : 0u;
                mma_f16_ss(tmem,       dAhi + ks * 2, dB0hi + ks * 2, IDESC, en);
                mma_f16_ss(tmem + 128, dAhi + ks * 2, dB1hi + ks * 2, IDESC, en);
                mma_f16_ss(tmem,       dAlo + ks * 2, dB0hi + ks * 2, IDESC, 1u);
                mma_f16_ss(tmem + 128, dAlo + ks * 2, dB1hi + ks * 2, IDESC, 1u);
                mma_f16_ss(tmem,       dAhi + ks * 2, dB0lo + ks * 2, IDESC, 1u);
                mma_f16_ss(tmem + 128, dAhi + ks * 2, dB1lo + ks * 2, IDESC, 1u);
            }
            tc_commit(empty_b + s * 8);
        }
    }

    {
        const int last = (K >> 5) - 1;
        mbar_wait(empty_b + (last & 3) * 8, (uint32_t)((last >> 2) & 1));
    }
    __syncthreads();
    tc_fence_after();
}
#endif

// ===== GEMM WIDE (generic epilogue modes) ==================================
template <int MODE>
__global__ __launch_bounds__(GTHREADS, 1)
void gemm_tcw(const __nv_bfloat16* __restrict__ a_hi, const __nv_bfloat16* __restrict__ a_lo,
              const __nv_bfloat16* __restrict__ b_hi, const __nv_bfloat16* __restrict__ b_lo,
              const float* __restrict__ bias, const float* __restrict__ res,
              float* __restrict__ out_f, __nv_bfloat16* __restrict__ out_hi,
              __nv_bfloat16* __restrict__ out_lo, int M, int N, int K)
{
#if TC_OK
    extern __shared__ char dynsmem[];
    __shared__ uint32_t sh_tmem;
    __shared__ __align__(8) uint64_t sh_full[WST];
    __shared__ __align__(8) uint64_t sh_empty[WST];

    const int tid = threadIdx.x;
    const int m0 = blockIdx.y * 128;
    const int n0 = blockIdx.x * 256;

    uint32_t sbase = smem_u32(dynsmem);
    sbase = (sbase + 1023u) & ~1023u;
    const uint32_t full_b = smem_u32(sh_full);
    const uint32_t empty_b = smem_u32(sh_empty);

    if (tid < 32) {
        tmem_alloc(smem_u32(&sh_tmem), 256);
        tmem_relinquish();
    }
    if (tid == 0) {
#pragma unroll
        for (int s = 0; s < WST; s++) {
            mbar_init(full_b + s * 8, 128);
            mbar_init(empty_b + s * 8, 1);
        }
    }
    __syncthreads();
    const uint32_t tmem = sh_tmem;

    wide_mainloop(sbase, tmem, full_b, empty_b, a_hi, a_lo, b_hi, b_lo, m0, n0, K, tid);

    if (tid < 128)
        gemm_epilogue_cols<MODE>(tmem, m0, n0, 256, tid, bias, res, out_f, out_hi, out_lo, N);
    __syncthreads();
    if (tid < 32) tmem_dealloc(tmem, 256);

#else
    // FFMA fallback (correctness only)
    __shared__ float As[16][128];
    __shared__ float Bs[16][32];
    const int tid = threadIdx.x;
    const int m0 = blockIdx.y * 128;
    const int n0 = blockIdx.x * 256;
    const int row = m0 + (tid & 127);
    for (int p = 0; p < 8; p++) {
        const int c0 = n0 + p * 32;
        float acc[32];
#pragma unroll
        for (int j = 0; j < 32; j++) acc[j] = 0.f;
        for (int kt = 0; kt < K; kt += 16) {
            __syncthreads();
            for (int i = tid; i < 16 * 128; i += GTHREADS) {
                const int kk = i >> 7, r = i & 127;
                const size_t g = (size_t)(m0 + r) * K + kt + kk;
                As[kk][r] = __bfloat162float(a_hi[g]) + __bfloat162float(a_lo[g]);
            }
            for (int i = tid; i < 16 * 32; i += GTHREADS) {
                const int kk = i >> 5, r = i & 31;
                const size_t g = (size_t)(c0 + r) * K + kt + kk;
                Bs[kk][r] = __bfloat162float(b_hi[g]) + __bfloat162float(b_lo[g]);
            }
            __syncthreads();
            if (tid < 128) {
#pragma unroll
                for (int kk = 0; kk < 16; kk++) {
                    const float a = As[kk][tid];
#pragma unroll
                    for (int j = 0; j < 32; j++) acc[j] = fmaf(a, Bs[kk][j], acc[j]);
                }
            }
        }
        if (tid < 128) {
#pragma unroll
            for (int j = 0; j < 32; j++) {
                const int c = c0 + j;
                float v = acc[j] + bias[c];
                if (MODE == 1) {
                    out_f[(size_t)row * N + c] = v + res[(size_t)row * N + c];
                } else if (MODE == 4) {
                    __nv_bfloat16 h, l;
                    bsplit(v, h, l);
                    const int b = row >> 11, s = row & 2047;
                    const size_t o = (((size_t)b * NHEAD + (c >> 6)) * HDIM + (c & 63)) * SEQ + s;
                    out_hi[o] = h;
                    out_lo[o] = l;
                } else {
                    if (MODE == 2) v = gelu_f(v);
                    __nv_bfloat16 h, l;
                    bsplit(v, h, l);
                    out_hi[(size_t)row * N + c] = h;
                    out_lo[(size_t)row * N + c] = l;
                }
            }
        }
        __syncthreads();
    }
#endif
}

// ===== FUSED QKV GEMM: one launch, N=3072, per-tile output routing =========
__global__ __launch_bounds__(GTHREADS, 1)
void gemm_qkv(const __nv_bfloat16* __restrict__ a_hi, const __nv_bfloat16* __restrict__ a_lo,
              const __nv_bfloat16* __restrict__ b_hi, const __nv_bfloat16* __restrict__ b_lo,
              const float* __restrict__ bq, const float* __restrict__ bk,
              const float* __restrict__ bv,
              __nv_bfloat16* __restrict__ qh, __nv_bfloat16* __restrict__ ql,
              __nv_bfloat16* __restrict__ kh, __nv_bfloat16* __restrict__ kl,
              __nv_bfloat16* __restrict__ vth, __nv_bfloat16* __restrict__ vtl)
{
    const int K = DIM;
#if TC_OK
    extern __shared__ char dynsmem[];
    __shared__ uint32_t sh_tmem;
    __shared__ __align__(8) uint64_t sh_full[WST];
    __shared__ __align__(8) uint64_t sh_empty[WST];

    const int tid = threadIdx.x;
    const int m0 = blockIdx.y * 128;
    const int n0 = blockIdx.x * 256;

    uint32_t sbase = smem_u32(dynsmem);
    sbase = (sbase + 1023u) & ~1023u;
    const uint32_t full_b = smem_u32(sh_full);
    const uint32_t empty_b = smem_u32(sh_empty);

    if (tid < 32) {
        tmem_alloc(smem_u32(&sh_tmem), 256);
        tmem_relinquish();
    }
    if (tid == 0) {
#pragma unroll
        for (int s = 0; s < WST; s++) {
            mbar_init(full_b + s * 8, 128);
            mbar_init(empty_b + s * 8, 1);
        }
    }
    __syncthreads();
    const uint32_t tmem = sh_tmem;

    wide_mainloop(sbase, tmem, full_b, empty_b, a_hi, a_lo, b_hi, b_lo, m0, n0, K, tid);

    if (tid < 128) {
        const int sel = n0 >> 10;                 // 0=Q, 1=K, 2=V (tile-constant)
        const int cbase = n0 & 1023;
        const float* bias = (sel == 0) ? bq : (sel == 1) ? bk : bv;
        if (sel < 2) {
            __nv_bfloat16* oh = sel ? kh : qh;
            __nv_bfloat16* ol = sel ? kl : ql;
            gemm_epilogue_cols<3>(tmem, m0, cbase, 256, tid, bias, nullptr,
                                  nullptr, oh, ol, DIM);
        } else {
            gemm_epilogue_cols<4>(tmem, m0, cbase, 256, tid, bias, nullptr,
                                  nullptr, vth, vtl, DIM);
        }
    }
    __syncthreads();
    if (tid < 32) tmem_dealloc(tmem, 256);

#else  // ===================== FFMA fallback ================================
    __shared__ float As[16][128];
    __shared__ float Bs[16][32];
    const int tid = threadIdx.x;
    const int m0 = blockIdx.y * 128;
    const int n0 = blockIdx.x * 256;
    const int row = m0 + (tid & 127);
    const int sel = n0 >> 10;
    const float* bias = (sel == 0) ? bq : (sel == 1) ? bk : bv;
    for (int p = 0; p < 8; p++) {
        const int c0 = n0 + p * 32;
        float acc[32];
#pragma unroll
        for (int j = 0; j < 32; j++) acc[j] = 0.f;
        for (int kt = 0; kt < K; kt += 16) {
            __syncthreads();
            for (int i = tid; i < 16 * 128; i += GTHREADS) {
                const int kk = i >> 7, r = i & 127;
                const size_t g = (size_t)(m0 + r) * K + kt + kk;
                As[kk][r] = __bfloat162float(a_hi[g]) + __bfloat162float(a_lo[g]);
            }
            for (int i = tid; i < 16 * 32; i += GTHREADS) {
                const int kk = i >> 5, r = i & 31;
                const size_t g = (size_t)(c0 + r) * K + kt + kk;
                Bs[kk][r] = __bfloat162float(b_hi[g]) + __bfloat162float(b_lo[g]);
            }
            __syncthreads();
            if (tid < 128) {
#pragma unroll
                for (int kk = 0; kk < 16; kk++) {
                    const float a = As[kk][tid];
#pragma unroll
                    for (int j = 0; j < 32; j++) acc[j] = fmaf(a, Bs[kk][j], acc[j]);
                }
            }
        }
        if (tid < 128) {
#pragma unroll
            for (int j = 0; j < 32; j++) {
                const int cg = c0 + j;
                const int c = cg & 1023;
                float v = acc[j] + bias[c];
                __nv_bfloat16 h, l;
                bsplit(v, h, l);
                if (sel < 2) {
                    __nv_bfloat16* oh = sel ? kh : qh;
                    __nv_bfloat16* ol = sel ? kl : ql;
                    oh[(size_t)row * DIM + c] = h;
                    ol[(size_t)row * DIM + c] = l;
                } else {
                    const int b = row >> 11, s = row & 2047;
                    const size_t o = (((size_t)b * NHEAD + (c >> 6)) * HDIM + (c & 63)) * SEQ + s;
                    vth[o] = h;
                    vtl[o] = l;
                }
            }
        }
        __syncthreads();
    }
#endif
}

// ===== GEMM NARROW: warp-spec, 128x128 tiles, K-tile 32, 3 stages, occ 2 ===
#define NST       3
#define NSTAGE_B  (4 * AH_T)                 // 32768
#define GSMEM_N   (NST * NSTAGE_B + 1024)

template <int MODE>
__global__ __launch_bounds__(GTHREADS, 2)
void gemm_tcn(const __nv_bfloat16* __restrict__ a_hi, const __nv_bfloat16* __restrict__ a_lo,
              const __nv_bfloat16* __restrict__ b_hi, const __nv_bfloat16* __restrict__ b_lo,
              const float* __restrict__ bias, const float* __restrict__ res,
              float* __restrict__ out_f, __nv_bfloat16* __restrict__ out_hi,
              __nv_bfloat16* __restrict__ out_lo, int M, int N, int K)
{
#if TC_OK
    extern __shared__ char dynsmem[];
    __shared__ uint32_t sh_tmem;
    __shared__ __align__(8) uint64_t sh_full[NST];
    __shared__ __align__(8) uint64_t sh_empty[NST];

    const int tid = threadIdx.x;
    const int m0 = blockIdx.y * 128;
    const int n0 = blockIdx.x * 128;

    uint32_t sbase = smem_u32(dynsmem);
    sbase = (sbase + 1023u) & ~1023u;
    const uint32_t full_b = smem_u32(sh_full);
    const uint32_t empty_b = smem_u32(sh_empty);

    if (tid < 32) {
        tmem_alloc(smem_u32(&sh_tmem), 128);
        tmem_relinquish();
    }
    if (tid == 0) {
#pragma unroll
        for (int s = 0; s < NST; s++) {
            mbar_init(full_b + s * 8, 128);
            mbar_init(empty_b + s * 8, 1);
        }
    }
    __syncthreads();
    const uint32_t tmem = sh_tmem;
    const int T = K >> 5;

    constexpr uint32_t IDESC =
        (1u << 4) | (1u << 7) | (1u << 10) | ((128u / 8u) << 17) | ((128u / 16u) << 24);

    if (tid >= 32) {
        const int ltid = tid - 32;
        for (int lt = 0; lt < T; lt++) {
            const int s = lt % 3, pass = lt / 3;
            if (pass >= 1) mbar_wait(empty_b + s * 8, (uint32_t)((pass - 1) & 1));
            const uint32_t sdst = sbase + s * NSTAGE_B;
            const int kc = (lt << 5);
#pragma unroll
            for (int i = 0; i < 16; i++) {
                const int c = ltid + i * 128;
                const int idx = c & 511;
                const int row = idx >> 2, ch = idx & 3;
                const uint32_t off = (uint32_t)(row * 64 + ch * 16);
                const uint32_t sw = off ^ ((off >> 3) & 0x30);
                const int sel = c >> 9;
                const __nv_bfloat16* base =
                    (sel == 0) ? a_hi : (sel == 1) ? a_lo : (sel == 2) ? b_hi : b_lo;
                const int r0 = (sel < 2) ? m0 : n0;
                cpasync16(sdst + (uint32_t)sel * AH_T + sw,
                          base + (size_t)(r0 + row) * K + kc + ch * 8);
            }
            cp_mbar_arrive_noinc(full_b + s * 8);
        }
    } else if (elect_one()) {
        tc_fence_after();
        for (int kt = 0; kt < T; kt++) {
            const int s = kt % 3, pass = kt / 3;
            mbar_wait(full_b + s * 8, (uint32_t)(pass & 1));
            const uint32_t st = sbase + s * NSTAGE_B;
            const uint64_t dAhi = make_desc64(st);
            const uint64_t dAlo = make_desc64(st + AH_T);
            const uint64_t dBhi = make_desc64(st + 2 * AH_T);
            const uint64_t dBlo = make_desc64(st + 3 * AH_T);
#pragma unroll
            for (int ks = 0; ks < 2; ks++) {
                const uint32_t en = (kt > 0 || ks > 0) ? 1u : 0u;
                mma_f16_ss(tmem, dAhi + ks * 2, dBhi + ks * 2, IDESC, en);
                mma_f16_ss(tmem, dAlo + ks * 2, dBhi + ks * 2, IDESC, 1u);
                mma_f16_ss(tmem, dAhi + ks * 2, dBlo + ks * 2, IDESC, 1u);
            }
            tc_commit(empty_b + s * 8);
        }
    }

    {
        const int last = T - 1;
        mbar_wait(empty_b + (last % 3) * 8, (uint32_t)((last / 3) & 1));
    }
    __syncthreads();
    tc_fence_after();

    if (tid < 128)
        gemm_epilogue_cols<MODE>(tmem, m0, n0, 128, tid, bias, res, out_f, out_hi, out_lo, N);
    __syncthreads();
    if (tid < 32) tmem_dealloc(tmem, 128);

#else
    // FFMA fallback (correctness only)
    __shared__ float As[16][128];
    __shared__ float Bs[16][32];
    const int tid = threadIdx.x;
    const int m0 = blockIdx.y * 128;
    const int n0 = blockIdx.x * 128;
    const int row = m0 + (tid & 127);
    for (int p = 0; p < 4; p++) {
        const int c0 = n0 + p * 32;
        float acc[32];
#pragma unroll
        for (int j = 0; j < 32; j++) acc[j] = 0.f;
        for (int kt = 0; kt < K; kt += 16) {
            __syncthreads();
            for (int i = tid; i < 16 * 128; i += GTHREADS) {
                const int kk = i >> 7, r = i & 127;
                const size_t g = (size_t)(m0 + r) * K + kt + kk;
                As[kk][r] = __bfloat162float(a_hi[g]) + __bfloat162float(a_lo[g]);
            }
            for (int i = tid; i < 16 * 32; i += GTHREADS) {
                const int kk = i >> 5, r = i & 31;
                const size_t g = (size_t)(c0 + r) * K + kt + kk;
                Bs[kk][r] = __bfloat162float(b_hi[g]) + __bfloat162float(b_lo[g]);
            }
            __syncthreads();
            if (tid < 128) {
#pragma unroll
                for (int kk = 0; kk < 16; kk++) {
                    const float a = As[kk][tid];
#pragma unroll
                    for (int j = 0; j < 32; j++) acc[j] = fmaf(a, Bs[kk][j], acc[j]);
                }
            }
        }
        if (tid < 128) {
#pragma unroll
            for (int j = 0; j < 32; j++) {
                const int c = c0 + j;
                float v = acc[j] + bias[c];
                if (MODE == 1) {
                    out_f[(size_t)row * N + c] = v + res[(size_t)row * N + c];
                } else {
                    if (MODE == 2) v = gelu_f(v);
                    __nv_bfloat16 h, l;
                    bsplit(v, h, l);
                    out_hi[(size_t)row * N + c] = h;
                    out_lo[(size_t)row * N + c] = l;
                }
            }
        }
        __syncthreads();
    }
#endif
}

// ======================= tcgen05 flash attention (8 warps) =================
// 256 threads. Warps 0-3 and 4-7 map to the same TMEM subpartitions, so the
// softmax splits S by column halves: warp w handles rows (w&3)*32+lane, cols
// (w>>2)*64..+64 -- halving per-thread exp/split work and giving 2 warps/SMSP
// to hide LDTM/MUFU/CVT latency. Per-row l is accumulated per-thread and the
// two column-half partials are combined once at the end via SMEM.
#define AQ_OFF   0
#define AK_OFF(b) (32768 + (b) * 32768)
#define AV_OFF(b) (98304 + (b) * 32768)
#define AP_OFF   163840
#define ASM_TOTAL (229376 + 1024)
#define ATHREADS 256

__global__ __launch_bounds__(ATHREADS, 1)
void attn_tc(const __nv_bfloat16* __restrict__ qhi, const __nv_bfloat16* __restrict__ qlo,
             const __nv_bfloat16* __restrict__ khi, const __nv_bfloat16* __restrict__ klo,
             const __nv_bfloat16* __restrict__ vthi, const __nv_bfloat16* __restrict__ vtlo,
             __nv_bfloat16* __restrict__ ohi, __nv_bfloat16* __restrict__ olo)
{
#if TC_OK
    extern __shared__ char dyn[];
    __shared__ uint32_t sh_tmem;
    __shared__ __align__(8) uint64_t sh_mb[3];
    __shared__ float sh_l[ATHREADS];

    const int tid = threadIdx.x;
    const int w = tid >> 5, lane = tid & 31;
    const int colh = w >> 2;                 // column half (0 or 1)
    const int srow = (w & 3) * 32 + lane;    // TMEM row this thread owns
    const int qblk = blockIdx.x, bh = blockIdx.y;
    const int b = bh >> 4, h = bh & 15;
    const int T = SEQ / 128;

    uint32_t sb = smem_u32(dyn);
    sb = (sb + 1023u) & ~1023u;
    char* dynb = (char*)dyn + (sb - smem_u32(dyn));
    const uint32_t mb = smem_u32(sh_mb);
    const uint32_t qkmb0 = mb, qkmb1 = mb + 8, pvmb = mb + 16;

    if (tid < 32) {
        tmem_alloc(smem_u32(&sh_tmem), 512);
        tmem_relinquish();
    }
    if (tid == 0) { mbar_init(qkmb0, 1); mbar_init(qkmb1, 1); mbar_init(pvmb, 1); }
    __syncthreads();
    const uint32_t TMB = sh_tmem;            // S0 @0, S1 @128, O @256

    const size_t koff0 = ((size_t)(b * SEQ)) * DIM + h * 64;
    const size_t voff0 = ((size_t)bh * 64) * SEQ;

    auto load_k = [&](int kt, int buf) {
        const uint32_t st = sb + AK_OFF(buf);
        const size_t koff = koff0 + (size_t)(kt * 128) * DIM;
        for (int c = tid; c < 2048; c += ATHREADS) {
            const int hl = c >> 10, r = (c >> 3) & 127, c16 = c & 7;
            const __nv_bfloat16* src = (hl ? klo : khi) + koff + (size_t)r * DIM + c16 * 8;
            uint32_t off = (uint32_t)(r * 128 + c16 * 16);
            off ^= (off >> 3) & 0x70;
            cpasync16(st + hl * 16384 + off, src);
        }
    };
    auto load_v = [&](int kt, int buf) {
        const uint32_t st = sb + AV_OFF(buf);
        const size_t voff = voff0 + kt * 128;
        for (int c = tid; c < 2048; c += ATHREADS) {
            const int tile = c >> 9, r = (c >> 3) & 63, c16 = c & 7;
            const int hl = tile >> 1, half = tile & 1;
            const __nv_bfloat16* src =
                (hl ? vtlo : vthi) + voff + (size_t)r * SEQ + half * 64 + c16 * 8;
            uint32_t off = (uint32_t)(r * 128 + c16 * 16);
            off ^= (off >> 3) & 0x70;
            cpasync16(st + tile * 8192 + off, src);
        }
    };

    constexpr uint32_t IDESC_QK =
        (1u << 4) | (1u << 7) | (1u << 10) | ((128u / 8u) << 17) | ((128u / 16u) << 24);
    constexpr uint32_t IDESC_PV =
        (1u << 4) | (1u << 7) | (1u << 10) | ((64u / 8u) << 17) | ((128u / 16u) << 24);

    const uint64_t dQhi = make_desc(sb + AQ_OFF), dQlo = make_desc(sb + AQ_OFF + 16384);

    auto issue_qk = [&](int kt) {
        const uint32_t sbuf = (uint32_t)(kt & 1);
        const uint32_t TS = TMB + sbuf * 128;
        const uint32_t st = sb + AK_OFF(kt & 1);
        const uint64_t dKhi = make_desc(st), dKlo = make_desc(st + 16384);
#pragma unroll
        for (int ks = 0; ks < 4; ks++)
            mma_f16_ss(TS, dQhi + ks * 2, dKhi + ks * 2, IDESC_QK, ks > 0 ? 1u : 0u);
#pragma unroll
        for (int ks = 0; ks < 4; ks++)
            mma_f16_ss(TS, dQlo + ks * 2, dKhi + ks * 2, IDESC_QK, 1u);
#pragma unroll
        for (int ks = 0; ks < 4; ks++)
            mma_f16_ss(TS, dQhi + ks * 2, dKlo + ks * 2, IDESC_QK, 1u);
        tc_commit((kt & 1) ? qkmb1 : qkmb0);
    };

    // prologue: Q + K0 (g0), K1 (g1), V0 (g2)
    {
        const size_t qoff = ((size_t)(b * SEQ + qblk * 128)) * DIM + h * 64;
        for (int c = tid; c < 2048; c += ATHREADS) {
            const int hl = c >> 10, r = (c >> 3) & 127, c16 = c & 7;
            const __nv_bfloat16* src = (hl ? qlo : qhi) + qoff + (size_t)r * DIM + c16 * 8;
            uint32_t off = (uint32_t)(r * 128 + c16 * 16);
            off ^= (off >> 3) & 0x70;
            cpasync16(sb + AQ_OFF + (hl ? 16384 : 0) + off, src);
        }
        load_k(0, 0);
        cp_commit();
        load_k(1, 1);
        cp_commit();
        load_v(0, 0);
        cp_commit();
    }
    cp_wait2();
    fence_proxy_async_shared();
    __syncthreads();
    if (tid < 32 && elect_one()) {
        tc_fence_after();
        issue_qk(0);
    }

    float l = 0.f;

    for (int kt = 0; kt < T; kt++) {
        const int sbuf = kt & 1;
        const uint32_t TS = TMB + sbuf * 128;
        const uint32_t TO = TMB + 256;

        mbar_wait(sbuf ? qkmb1 : qkmb0, (uint32_t)((kt >> 1) & 1));
        tc_fence_after();

        cp_wait1();
        fence_proxy_async_shared();
        __syncthreads();
        if (kt + 1 < T) {
            if (tid < 32 && elect_one()) {
                tc_fence_after();
                issue_qk(kt + 1);
            }
        }

        if (kt + 2 < T) load_k(kt + 2, sbuf);
        cp_commit();

        if (kt >= 1) mbar_wait(pvmb, (uint32_t)((kt - 1) & 1));
        if (kt + 1 < T) load_v(kt + 1, (kt + 1) & 1);
        cp_commit();

        // softmax: warp w covers rows (w&3)*32+lane, cols colh*64..+64
#pragma unroll
        for (int c0 = 0; c0 < 64; c0 += 32) {
            uint32_t sr[32];
            tmem_ld32(sr, TS + colh * 64 + c0);
            tmem_wait_ld();
            float p[32];
#pragma unroll
            for (int j = 0; j < 32; j++) {
                p[j] = __expf(__uint_as_float(sr[j]) * 0.125f);
                l += p[j];
            }
            const int cb = c0 * 2;       // byte offset within P half-tile row
#pragma unroll
            for (int g = 0; g < 4; g++) {
                ushort hs[8], ls[8];
#pragma unroll
                for (int e = 0; e < 8; e++) {
                    __nv_bfloat16 hb, lb;
                    bsplit(p[g * 8 + e], hb, lb);
                    hs[e] = __bfloat16_as_ushort(hb);
                    ls[e] = __bfloat16_as_ushort(lb);
                }
                uint32_t off = (uint32_t)(srow * 128 + cb + g * 16);
                off ^= (off >> 3) & 0x70;
                *(uint4*)(dynb + AP_OFF + colh * 16384 + off) = *(uint4*)hs;
                *(uint4*)(dynb + AP_OFF + 32768 + colh * 16384 + off) = *(uint4*)ls;
            }
        }
        tc_fence_before();

        asm volatile("cp.async.wait_group 2;" ::: "memory");
        fence_proxy_async_shared();
        __syncthreads();
        if (tid < 32 && elect_one()) {
            tc_fence_after();
            const uint32_t vst = sb + AV_OFF(sbuf);
            int first = (kt == 0);
#pragma unroll
            for (int half = 0; half < 2; half++) {
                const uint64_t dPh = make_desc(sb + AP_OFF + half * 16384);
                const uint64_t dPl = make_desc(sb + AP_OFF + 32768 + half * 16384);
                const uint64_t dVh = make_desc(vst + half * 8192);
                const uint64_t dVl = make_desc(vst + (2 + half) * 8192);
#pragma unroll
                for (int ks = 0; ks < 4; ks++) {
                    mma_f16_ss(TO, dPh + ks * 2, dVh + ks * 2, IDESC_PV, first ? 0u : 1u);
                    first = 0;
                    mma_f16_ss(TO, dPl + ks * 2, dVh + ks * 2, IDESC_PV, 1u);
                    mma_f16_ss(TO, dPh + ks * 2, dVl + ks * 2, IDESC_PV, 1u);
                }
            }
            tc_commit(pvmb);
        }
    }

    // combine per-row l partials (rows owned by threads t and t+128)
    sh_l[tid] = l;
    mbar_wait(pvmb, (uint32_t)((T - 1) & 1));
    __syncthreads();
    tc_fence_after();

    // drain O once: warp w drains rows (w&3)*32+lane, cols colh*32..+32
    {
        const float inv = 1.0f / (sh_l[srow] + sh_l[srow + 128]);
        uint32_t pr[32];
        tmem_ld32(pr, TMB + 256 + colh * 32);
        tmem_wait_ld();
        const size_t obase =
            ((size_t)(b * SEQ + qblk * 128 + srow)) * DIM + h * 64 + colh * 32;
#pragma unroll
        for (int j0 = 0; j0 < 32; j0 += 4) {
            ushort hs[4], ls[4];
#pragma unroll
            for (int jj = 0; jj < 4; jj++) {
                __nv_bfloat16 hb, lb;
                bsplit(__uint_as_float(pr[j0 + jj]) * inv, hb, lb);
                hs[jj] = __bfloat16_as_ushort(hb);
                ls[jj] = __bfloat16_as_ushort(lb);
            }
            *(ushort4*)(ohi + obase + j0) = make_ushort4(hs[0], hs[1], hs[2], hs[3]);
            *(ushort4*)(olo + obase + j0) = make_ushort4(ls[0], ls[1], ls[2], ls[3]);
        }
    }
    tc_fence_before();
    __syncthreads();
    if (tid < 32) tmem_dealloc(sh_tmem, 512);

#else  // fallback fp32 attention (256 threads; compute on first 128)
    const int bh = blockIdx.y;
    const int b = bh >> 4;
    const int qrow = blockIdx.x * 128 + (threadIdx.x & 127);
    const bool act = threadIdx.x < 128;
    const size_t qkbase = ((size_t)b * SEQ) * DIM + (size_t)(bh & 15) * HDIM;
    const size_t vbase = ((size_t)bh * HDIM) * SEQ;

    float q[HDIM];
    if (act) {
        const __nv_bfloat16* qph = qhi + qkbase + (size_t)qrow * DIM;
        const __nv_bfloat16* qpl = qlo + qkbase + (size_t)qrow * DIM;
#pragma unroll
        for (int d = 0; d < HDIM; d++)
            q[d] = __bfloat162float(qph[d]) + __bfloat162float(qpl[d]);
    }
    float o[HDIM];
#pragma unroll
    for (int d = 0; d < HDIM; d++) o[d] = 0.f;
    float l = 0.f;

    __shared__ float Ks[32][HDIM];
    __shared__ float Vs[32][HDIM];

    for (int kt = 0; kt < SEQ / 32; kt++) {
        __syncthreads();
        const int kbase = kt * 32;
        for (int i = threadIdx.x; i < 32 * HDIM; i += ATHREADS) {
            const int j = i >> 6, d = i & 63;
            const size_t g = qkbase + (size_t)(kbase + j) * DIM + d;
            Ks[j][d] = __bfloat162float(khi[g]) + __bfloat162float(klo[g]);
            const size_t gv = vbase + (size_t)d * SEQ + kbase + j;
            Vs[j][d] = __bfloat162float(vthi[gv]) + __bfloat162float(vtlo[gv]);
        }
        __syncthreads();

        if (act) {
#pragma unroll
            for (int j = 0; j < 32; j++) {
                float s = 0.f;
#pragma unroll
                for (int d = 0; d < HDIM; d++) s = fmaf(q[d], Ks[j][d], s);
                const float p = __expf(s * 0.125f);
                l += p;
#pragma unroll
                for (int d = 0; d < HDIM; d++) o[d] = fmaf(p, Vs[j][d], o[d]);
            }
        }
    }

    if (act) {
        const float inv = 1.0f / l;
        const size_t ob = qkbase + (size_t)qrow * DIM;
#pragma unroll
        for (int d = 0; d < HDIM; d++) {
            __nv_bfloat16 hb, lb;
            bsplit(o[d] * inv, hb, lb);
            ohi[ob + d] = hb;
            olo[ob + d] = lb;
        }
    }
#endif
}

// ======================= launch ============================================
extern "C" void kernel_launch(void* const* d_in, const int* in_sizes, int n_in,
                              void* d_out, int out_size)
{
    const float* feature = (const float*)d_in[0];
    const float* wq = (const float*)d_in[2];
    const float* bq = (const float*)d_in[3];
    const float* wk = (const float*)d_in[4];
    const float* bk = (const float*)d_in[5];
    const float* wv = (const float*)d_in[6];
    const float* bv = (const float*)d_in[7];
    const float* wo = (const float*)d_in[8];
    const float* bo = (const float*)d_in[9];
    const float* ln1g = (const float*)d_in[10];
    const float* ln1b = (const float*)d_in[11];
    const float* ln2g = (const float*)d_in[12];
    const float* ln2b = (const float*)d_in[13];
    const float* w1 = (const float*)d_in[14];
    const float* b1 = (const float*)d_in[15];
    const float* w2 = (const float*)d_in[16];
    const float* b2 = (const float*)d_in[17];
    float* out = (float*)d_out;

    __nv_bfloat16 *xln1h, *xln1l, *attnh, *attnl, *xln2h, *xln2l, *h1h, *h1l;
    __nv_bfloat16 *qh, *ql, *kh, *kl, *vth, *vtl;
    __nv_bfloat16 *wqkvh, *wqkvl, *woh, *wol, *w1h, *w1l, *w2h, *w2l;
    float *feat;
    cudaGetSymbolAddress((void**)&xln1h, g_xln1_hi);
    cudaGetSymbolAddress((void**)&xln1l, g_xln1_lo);
    cudaGetSymbolAddress((void**)&qh, g_q_hi);  cudaGetSymbolAddress((void**)&ql, g_q_lo);
    cudaGetSymbolAddress((void**)&kh, g_k_hi);  cudaGetSymbolAddress((void**)&kl, g_k_lo);
    cudaGetSymbolAddress((void**)&vth, g_vt_hi); cudaGetSymbolAddress((void**)&vtl, g_vt_lo);
    cudaGetSymbolAddress((void**)&attnh, g_attn_hi);
    cudaGetSymbolAddress((void**)&attnl, g_attn_lo);
    cudaGetSymbolAddress((void**)&feat, g_feat);
    cudaGetSymbolAddress((void**)&xln2h, g_xln2_hi);
    cudaGetSymbolAddress((void**)&xln2l, g_xln2_lo);
    cudaGetSymbolAddress((void**)&h1h, g_h1_hi);
    cudaGetSymbolAddress((void**)&h1l, g_h1_lo);
    cudaGetSymbolAddress((void**)&wqkvh, g_wqkvT_hi);
    cudaGetSymbolAddress((void**)&wqkvl, g_wqkvT_lo);
    cudaGetSymbolAddress((void**)&woh, g_woT_hi); cudaGetSymbolAddress((void**)&wol, g_woT_lo);
    cudaGetSymbolAddress((void**)&w1h, g_w1T_hi); cudaGetSymbolAddress((void**)&w1l, g_w1T_lo);
    cudaGetSymbolAddress((void**)&w2h, g_w2T_hi); cudaGetSymbolAddress((void**)&w2l, g_w2T_lo);

    cudaFuncSetAttribute(gemm_qkv, cudaFuncAttributeMaxDynamicSharedMemorySize, GSMEM_W);
    cudaFuncSetAttribute(gemm_tcw<1>, cudaFuncAttributeMaxDynamicSharedMemorySize, GSMEM_W);
    cudaFuncSetAttribute(gemm_tcn<1>, cudaFuncAttributeMaxDynamicSharedMemorySize, GSMEM_N);
    cudaFuncSetAttribute(gemm_tcn<2>, cudaFuncAttributeMaxDynamicSharedMemorySize, GSMEM_N);
    cudaFuncSetAttribute(attn_tc, cudaFuncAttributeMaxDynamicSharedMemorySize, ASM_TOTAL);

    // all weight conversions in ONE launch (QKV into fused buffer)
    wtrans_all<<<12288, 256>>>(wq, wk, wv, wo, w1, w2,
                               wqkvh, wqkvl, woh, wol, w1h, w1l, w2h, w2l);

    // LN1
    ln_kernel<<<NTOK, 256>>>(feature, ln1g, ln1b, xln1h, xln1l);

    // FUSED QKV: one wide GEMM, N=3072, per-tile output routing
    gemm_qkv<<<dim3(3 * DIM / 256, NTOK / 128), GTHREADS, GSMEM_W>>>(
        xln1h, xln1l, wqkvh, wqkvl, bq, bk, bv, qh, ql, kh, kl, vth, vtl);

    // attention (tcgen05 flash, 8-warp softmax, O accumulated in TMEM)
    attn_tc<<<dim3(SEQ / 128, Bz * NHEAD), ATHREADS, ASM_TOTAL>>>(qh, ql, kh, kl, vth, vtl,
                                                                  attnh, attnl);

    // O projection + residual(feature): WIDE
    gemm_tcw<1><<<dim3(DIM / 256, NTOK / 128), GTHREADS, GSMEM_W>>>(
        attnh, attnl, woh, wol, bo, feature, feat, nullptr, nullptr, NTOK, DIM, DIM);

    // LN2
    ln_kernel<<<NTOK, 256>>>(feat, ln2g, ln2b, xln2h, xln2l);

    // FFN up + GELU: NARROW (multi-wave; R12 evidence)
    gemm_tcn<2><<<dim3(FF / 128, NTOK / 128), GTHREADS, GSMEM_N>>>(
        xln2h, xln2l, w1h, w1l, b1, nullptr, nullptr, h1h, h1l, NTOK, FF, DIM);

    // FFN down + residual(feat) -> out: NARROW
    gemm_tcn<1><<<dim3(DIM / 128, NTOK / 128), GTHREADS, GSMEM_N>>>(
        h1h, h1l, w2h, w2l, b2, feat, out, nullptr, nullptr, NTOK, DIM, FF);
}